// round 6
// baseline (speedup 1.0000x reference)
#include <cuda_runtime.h>
#include <cstdint>

#define B_SZ 512
#define T_SZ 128
#define NBLK 144
#define SMEM_PERSIST 223232
#define SMEM_PROJ    110592

// ---------------- __device__ scratch (no allocations allowed) ----------------
__device__ __align__(128) float g_xg0[(size_t)T_SZ * B_SZ * 1024];
__device__ __align__(128) float g_xg1[(size_t)T_SZ * B_SZ * 256];
__device__ __align__(128) float g_xg2[(size_t)T_SZ * B_SZ * 256];
__device__ __align__(128) float g_xp0[(size_t)65536 * 304]; // K pair-swizzled
__device__ __align__(128) float g_xp1[(size_t)65536 * 80];
__device__ __align__(128) float g_xp2[(size_t)65536 * 48];
__device__ __align__(128) float g_wih0[1024 * 304];         // K pair-swizzled
__device__ __align__(128) float g_wih1[256 * 80];
__device__ __align__(128) float g_wih2[256 * 48];
__device__ __align__(128) float g_whh0[1024 * 256];         // K pair-swizzled
__device__ __align__(128) float g_whh1[256 * 64];
__device__ __align__(128) float g_whh2[256 * 64];
__device__ __align__(128) float g_bias0[1024];
__device__ __align__(128) float g_bias1[256];
__device__ __align__(128) float g_bias2[256];
__device__ __align__(128) float g_h0[2][B_SZ * 256];        // hidden pair-swizzled, tf32
__device__ __align__(128) float g_h1[2][B_SZ * 64];
__device__ __align__(128) float g_h2[2][B_SZ * 64];
__device__ __align__(128) float g_c1[B_SZ * 64];
__device__ __align__(128) float g_c2[B_SZ * 64];
__device__ __align__(128) unsigned g_bar0[16 * 32];         // one counter per bm group

// ---------------- helpers ----------------
__device__ __forceinline__ int swz(int k) {
    return (k & ~7) | ((k & 3) << 1) | ((k >> 2) & 1);
}

__device__ __forceinline__ float tf32r(float x) {
    uint32_t u;
    asm("cvt.rna.tf32.f32 %0, %1;" : "=r"(u) : "f"(x));
    return __uint_as_float(u);
}

__device__ __forceinline__ void mma_tf32(float c[4], const uint32_t a[4], const uint32_t b[2]) {
    asm volatile(
        "mma.sync.aligned.m16n8k8.row.col.f32.tf32.tf32.f32 "
        "{%0,%1,%2,%3}, {%4,%5,%6,%7}, {%8,%9}, {%0,%1,%2,%3};"
        : "+f"(c[0]), "+f"(c[1]), "+f"(c[2]), "+f"(c[3])
        : "r"(a[0]), "r"(a[1]), "r"(a[2]), "r"(a[3]), "r"(b[0]), "r"(b[1]));
}

__device__ __forceinline__ float fex2(float x) {
    float r; asm("ex2.approx.f32 %0, %1;" : "=f"(r) : "f"(x)); return r;
}
__device__ __forceinline__ float frcp(float x) {
    float r; asm("rcp.approx.f32 %0, %1;" : "=f"(r) : "f"(x)); return r;
}
__device__ __forceinline__ float sigm(float x) {
    return frcp(1.0f + fex2(-1.4426950408889634f * x));
}
__device__ __forceinline__ float tanhfast(float x) {
    return 2.0f * frcp(1.0f + fex2(-2.8853900817779268f * x)) - 1.0f;
}

__device__ __forceinline__ void cpasync16(void* dst, const void* src) {
    uint32_t d = (uint32_t)__cvta_generic_to_shared(dst);
    asm volatile("cp.async.ca.shared.global [%0], [%1], 16;" :: "r"(d), "l"(src));
}
// cg (L2-only) — REQUIRED for h ping-pong (peer-SM writes; .ca would hit stale L1)
__device__ __forceinline__ void cpasync16cg(void* dst, const void* src) {
    uint32_t d = (uint32_t)__cvta_generic_to_shared(dst);
    asm volatile("cp.async.cg.shared.global [%0], [%1], 16;" :: "r"(d), "l"(src));
}
#define CP_COMMIT asm volatile("cp.async.commit_group;")
#define CP_WAIT1  asm volatile("cp.async.wait_group 1;")
#define CP_WAIT0  asm volatile("cp.async.wait_group 0;")

// ---------------- launch 0: prep weights (gate-interleave + K-swizzle + tf32) ----------
__global__ void prep_w_kernel(
    const float* __restrict__ wih0, const float* __restrict__ whh0,
    const float* __restrict__ bih0, const float* __restrict__ bhh0,
    const float* __restrict__ wih1, const float* __restrict__ whh1,
    const float* __restrict__ bih1, const float* __restrict__ bhh1,
    const float* __restrict__ wih2, const float* __restrict__ whh2,
    const float* __restrict__ bih2, const float* __restrict__ bhh2)
{
    size_t stride = (size_t)gridDim.x * blockDim.x;
    size_t t0 = (size_t)blockIdx.x * blockDim.x + threadIdx.x;

    for (size_t ii = t0; ii < 1024 * 304; ii += stride) {
        int i = (int)ii;
        int gp = i / 304, dp = i - gp * 304;
        int k = gp >> 2, q = gp & 3, go = q * 256 + k;
        g_wih0[gp * 304 + swz(dp)] = (dp < 300) ? tf32r(wih0[go * 300 + dp]) : 0.0f;
    }
    for (size_t ii = t0; ii < 256 * 80; ii += stride) {
        int i = (int)ii;
        int gp = i / 80, dp = i - gp * 80;
        int k = gp >> 2, q = gp & 3, go = q * 64 + k;
        g_wih1[gp * 80 + swz(dp)] = (dp < 74) ? tf32r(wih1[go * 74 + dp]) : 0.0f;
    }
    for (size_t ii = t0; ii < 256 * 48; ii += stride) {
        int i = (int)ii;
        int gp = i / 48, dp = i - gp * 48;
        int k = gp >> 2, q = gp & 3, go = q * 64 + k;
        g_wih2[gp * 48 + swz(dp)] = (dp < 35) ? tf32r(wih2[go * 35 + dp]) : 0.0f;
    }
    for (size_t ii = t0; ii < 1024 * 256; ii += stride) {
        int i = (int)ii;
        int gp = i >> 8, dp = i & 255;
        int k = gp >> 2, q = gp & 3, go = q * 256 + k;
        g_whh0[gp * 256 + swz(dp)] = tf32r(whh0[go * 256 + dp]);
    }
    for (size_t ii = t0; ii < 256 * 64; ii += stride) {
        int i = (int)ii;
        int gp = i >> 6, dp = i & 63;
        int k = gp >> 2, q = gp & 3, go = q * 64 + k;
        g_whh1[gp * 64 + swz(dp)] = tf32r(whh1[go * 64 + dp]);
        g_whh2[gp * 64 + swz(dp)] = tf32r(whh2[go * 64 + dp]);
    }
    for (size_t ii = t0; ii < 1024; ii += stride) {
        int i = (int)ii;
        int k = i >> 2, q = i & 3, go = q * 256 + k;
        g_bias0[i] = bih0[go] + bhh0[go];
    }
    for (size_t ii = t0; ii < 256; ii += stride) {
        int i = (int)ii;
        int k = i >> 2, q = i & 3, go = q * 64 + k;
        g_bias1[i] = bih1[go] + bhh1[go];
        g_bias2[i] = bih2[go] + bhh2[go];
    }
}

// ---------------- launch 1: pad x -> xp (tf32 + K pair-swizzle) ----------------
__global__ void prep_x_kernel(
    const float* __restrict__ x0, const float* __restrict__ x1, const float* __restrict__ x2)
{
    size_t stride = (size_t)gridDim.x * blockDim.x;
    size_t t0 = (size_t)blockIdx.x * blockDim.x + threadIdx.x;

    for (size_t i = t0; i < (size_t)65536 * 304; i += stride) {
        int r = (int)(i / 304), d = (int)(i - (size_t)r * 304);
        g_xp0[(size_t)r * 304 + swz(d)] = (d < 300) ? tf32r(x0[(size_t)r * 300 + d]) : 0.0f;
    }
    for (size_t i = t0; i < (size_t)65536 * 80; i += stride) {
        int r = (int)(i / 80), d = (int)(i - (size_t)r * 80);
        g_xp1[(size_t)r * 80 + swz(d)] = (d < 74) ? tf32r(x1[(size_t)r * 74 + d]) : 0.0f;
    }
    for (size_t i = t0; i < (size_t)65536 * 48; i += stride) {
        int r = (int)(i / 48), d = (int)(i - (size_t)r * 48);
        g_xp2[(size_t)r * 48 + swz(d)] = (d < 35) ? tf32r(x2[(size_t)r * 35 + d]) : 0.0f;
    }
}

// ---------------- launch 2: init ----------------
__global__ void init_kernel() {
    int stride = gridDim.x * blockDim.x;
    int i0 = blockIdx.x * blockDim.x + threadIdx.x;
    for (int i = i0; i < 16 * 32; i += stride) g_bar0[i] = 0u;
    for (int i = i0; i < B_SZ * 256; i += stride) g_h0[0][i] = 0.0f;
    for (int i = i0; i < B_SZ * 64; i += stride) {
        g_h1[0][i] = 0.0f; g_c1[i] = 0.0f;
        g_h2[0][i] = 0.0f; g_c2[i] = 0.0f;
    }
}

// ---------------- launch 3: all input projections, 128x256 tiles, 3-stage cp.async ------
__device__ __forceinline__ void proj_impl(
    const float* __restrict__ XP, const float* __restrict__ W,
    const float* __restrict__ bias, float* __restrict__ XG,
    int DP, int G, int KT, int colBase, int rowBase, float* xs, float* ws)
{
    int tid = threadIdx.x, lane = tid & 31, warp = tid >> 5;
    int gp = lane >> 2, tg = lane & 3;
    int wm = warp >> 1, wn = warp & 1; // 4m x 2n warps; warp tile 32 x 128

    float acc[2][16][4];
#pragma unroll
    for (int i = 0; i < 2; i++)
#pragma unroll
        for (int j = 0; j < 16; j++)
#pragma unroll
            for (int v = 0; v < 4; v++) acc[i][j][v] = 0.0f;

    auto issue = [&](int kt, int s) {
        int k0 = kt * 16;
        float* xd = xs + s * 3072;
        float* wd = ws + s * 6144;
#pragma unroll
        for (int j = 0; j < 2; j++) {
            int id = tid + j * 256;
            int r = id >> 2, c = id & 3;
            cpasync16(&xd[r * 24 + c * 4], &XP[(size_t)(rowBase + r) * DP + k0 + c * 4]);
        }
#pragma unroll
        for (int j = 0; j < 4; j++) {
            int id = tid + j * 256;
            int r = id >> 2, c = id & 3;
            cpasync16(&wd[r * 24 + c * 4], &W[(size_t)(colBase + r) * DP + k0 + c * 4]);
        }
        CP_COMMIT;
    };

    issue(0, 0);
    issue(1, 1);

    for (int kt = 0; kt < KT; kt++) {
        int s = kt % 3;
        if (kt + 1 < KT) { CP_WAIT1; } else { CP_WAIT0; }
        __syncthreads();
        float* xb = xs + s * 3072;
        float* wb = ws + s * 6144;
#pragma unroll
        for (int kk = 0; kk < 2; kk++) {
            uint32_t a[2][4];
#pragma unroll
            for (int mt = 0; mt < 2; mt++) {
                int ar = (wm * 32 + mt * 16 + gp) * 24 + kk * 8 + tg * 2;
                float2 lo = *(float2*)&xb[ar];
                float2 hi = *(float2*)&xb[ar + 8 * 24];
                a[mt][0] = __float_as_uint(lo.x);
                a[mt][1] = __float_as_uint(hi.x);
                a[mt][2] = __float_as_uint(lo.y);
                a[mt][3] = __float_as_uint(hi.y);
            }
#pragma unroll
            for (int nt = 0; nt < 16; nt++) {
                int br = (wn * 128 + nt * 8 + gp) * 24 + kk * 8 + tg * 2;
                float2 bv = *(float2*)&wb[br];
                uint32_t b[2] = {__float_as_uint(bv.x), __float_as_uint(bv.y)};
#pragma unroll
                for (int mt = 0; mt < 2; mt++) mma_tf32(acc[mt][nt], a[mt], b);
            }
        }
        if (kt + 2 < KT) issue(kt + 2, (kt + 2) % 3);
        __syncthreads();
    }

#pragma unroll
    for (int mt = 0; mt < 2; mt++)
#pragma unroll
        for (int nt = 0; nt < 16; nt++) {
            int r0 = rowBase + wm * 32 + mt * 16 + gp;
            int col = colBase + wn * 128 + nt * 8 + 2 * tg;
            float bx = bias[col], by = bias[col + 1];
            int tt0 = r0 & 127, bb0 = r0 >> 7;
            *(float2*)&XG[((size_t)tt0 * B_SZ + bb0) * G + col] =
                make_float2(acc[mt][nt][0] + bx, acc[mt][nt][1] + by);
            int r1 = r0 + 8;
            int tt1 = r1 & 127, bb1 = r1 >> 7;
            *(float2*)&XG[((size_t)tt1 * B_SZ + bb1) * G + col] =
                make_float2(acc[mt][nt][2] + bx, acc[mt][nt][3] + by);
        }
}

__global__ __launch_bounds__(256) void proj_all_kernel() {
    extern __shared__ __align__(16) float psm[];
    float* xs = psm;            // 3 x 128x24
    float* ws = psm + 3 * 3072; // 3 x 256x24
    int bx = blockIdx.x;
    int rowBase = blockIdx.y * 128;
    if (bx < 4) {
        proj_impl(g_xp0, g_wih0, g_bias0, g_xg0, 304, 1024, 19, bx * 256, rowBase, xs, ws);
    } else if (bx == 4) {
        proj_impl(g_xp1, g_wih1, g_bias1, g_xg1, 80, 256, 5, 0, rowBase, xs, ws);
    } else {
        proj_impl(g_xp2, g_wih2, g_bias2, g_xg2, 48, 256, 3, 0, rowBase, xs, ws);
    }
}

// ---------------- launch 4: persistent recurrence ----------------
// blocks 0..127  : m0, block = 32 batch rows x 128 gate cols; per-bm 8-block barrier
// blocks 128..143: m1/m2, block = 64 batch rows x all 256 gate cols; fully independent
__global__ __launch_bounds__(256, 1) void persist_kernel() {
    extern __shared__ __align__(16) float sm[];
    int bid = blockIdx.x, tid = threadIdx.x;
    int lane = tid & 31, warp = tid >> 5;
    int gp = lane >> 2, tg = lane & 3;

    if (bid < 128) {
        // ================= module 0: H=256, G=1024 =================
        int bm = bid >> 3, bn = bid & 7;
        int rowBase = bm * 32, colBase = bn * 128;
        float* hs   = sm;                  // 32 x 264
        float* xbuf = sm + 8448;           // 32 x 128
        float* gsm  = sm + 8448 + 4096;    // 32 x 128

        // weights resident in registers: warp owns cols [wn*16, wn*16+16), all K
        int wn = warp;
        uint32_t breg[32][2][2];
#pragma unroll
        for (int kk = 0; kk < 32; kk++)
#pragma unroll
            for (int nt = 0; nt < 2; nt++) {
                float2 v = *(const float2*)
                    &g_whh0[(size_t)(colBase + wn * 16 + nt * 8 + gp) * 256 + kk * 8 + tg * 2];
                breg[kk][nt][0] = __float_as_uint(v.x);
                breg[kk][nt][1] = __float_as_uint(v.y);
            }

        float creg[4] = {0.0f, 0.0f, 0.0f, 0.0f};
        unsigned* cnt = &g_bar0[bm * 32];

        for (int t = 0; t < T_SZ; t++) {
            const float* hin = g_h0[t & 1];
            float* hout = g_h0[(t & 1) ^ 1];
            const float* xg = g_xg0 + (size_t)t * B_SZ * 1024;

            // group A: h (cg, needed for MMA). group B: xg (cold DRAM; hides under MMA)
#pragma unroll
            for (int j = 0; j < 8; j++) {
                int id = tid + j * 256;
                int r = id >> 6, c = id & 63;
                cpasync16cg(&hs[r * 264 + c * 4], &hin[(rowBase + r) * 256 + c * 4]);
            }
            CP_COMMIT;
#pragma unroll
            for (int j = 0; j < 4; j++) {
                int id = tid + j * 256;
                int r = id >> 5, c = id & 31;
                cpasync16(&xbuf[r * 128 + c * 4],
                          &xg[(size_t)(rowBase + r) * 1024 + colBase + c * 4]);
            }
            CP_COMMIT;
            CP_WAIT1; // h arrived; xg still in flight
            __syncthreads();

            float acc[2][2][4];
#pragma unroll
            for (int i = 0; i < 2; i++)
#pragma unroll
                for (int j = 0; j < 2; j++)
#pragma unroll
                    for (int v = 0; v < 4; v++) acc[i][j][v] = 0.0f;

#pragma unroll
            for (int kk = 0; kk < 32; kk++) {
                int kb = kk * 8 + tg * 2;
                float2 lo0 = *(float2*)&hs[gp * 264 + kb];
                float2 hi0 = *(float2*)&hs[(gp + 8) * 264 + kb];
                float2 lo1 = *(float2*)&hs[(gp + 16) * 264 + kb];
                float2 hi1 = *(float2*)&hs[(gp + 24) * 264 + kb];
                uint32_t a0[4] = {__float_as_uint(lo0.x), __float_as_uint(hi0.x),
                                  __float_as_uint(lo0.y), __float_as_uint(hi0.y)};
                uint32_t a1[4] = {__float_as_uint(lo1.x), __float_as_uint(hi1.x),
                                  __float_as_uint(lo1.y), __float_as_uint(hi1.y)};
                mma_tf32(acc[0][0], a0, breg[kk][0]);
                mma_tf32(acc[0][1], a0, breg[kk][1]);
                mma_tf32(acc[1][0], a1, breg[kk][0]);
                mma_tf32(acc[1][1], a1, breg[kk][1]);
            }

#pragma unroll
            for (int mt = 0; mt < 2; mt++)
#pragma unroll
                for (int nt = 0; nt < 2; nt++) {
                    int r = mt * 16 + gp, col = wn * 16 + nt * 8 + tg * 2;
                    *(float2*)&gsm[r * 128 + col] =
                        make_float2(acc[mt][nt][0], acc[mt][nt][1]);
                    *(float2*)&gsm[(r + 8) * 128 + col] =
                        make_float2(acc[mt][nt][2], acc[mt][nt][3]);
                }
            CP_WAIT0; // xg (long since arrived)
            __syncthreads();

#pragma unroll
            for (int j = 0; j < 4; j++) {
                int idx = tid + j * 256;
                int bl = idx >> 5, kl = idx & 31;
                float4 gt = *(float4*)&gsm[bl * 128 + 4 * kl];
                float4 xv = *(float4*)&xbuf[bl * 128 + 4 * kl];
                float ii = sigm(gt.x + xv.x);
                float ff = sigm(gt.y + xv.y);
                float gg = tanhfast(gt.z + xv.z);
                float oo = sigm(gt.w + xv.w);
                float cn = ff * creg[j] + ii * gg;
                creg[j] = cn;
                float hn = oo * tanhfast(cn);
                hout[(rowBase + bl) * 256 + swz(bn * 32 + kl)] = tf32r(hn);
            }

            if (t + 1 < T_SZ) {
                __syncthreads();
                if (tid == 0) {
                    __threadfence();
                    atomicAdd(cnt, 1u);
                    unsigned tgt = 8u * (unsigned)(t + 1);
                    while (*(volatile unsigned*)cnt < tgt) {}
                    __threadfence();
                }
                __syncthreads();
            }
        }
    } else {
        // ================= modules 1,2: H=64, G=256, fully independent ============
        int sub = bid - 128;
        int mod = sub >> 3, bm = sub & 7;
        int rowBase = bm * 64;
        const float* whh = mod ? g_whh2 : g_whh1;
        const float* xgb = mod ? g_xg2 : g_xg1;
        float* cb = mod ? g_c2 : g_c1;

        float* ws   = sm;                           // 256 x 72
        float* hs   = sm + 256 * 72;                // 64 x 72
        float* gsm  = sm + 256 * 72 + 64 * 72;      // 64 x 256
        float* xbuf = gsm + 64 * 256;               // 64 x 256

        for (int idx = tid; idx < 256 * 16; idx += 256) {
            int r = idx >> 4, c = idx & 15;
            *(float4*)&ws[r * 72 + c * 4] = *(const float4*)&whh[r * 64 + c * 4];
        }

        int wm = warp >> 2, wn = warp & 3;

        for (int t = 0; t < T_SZ; t++) {
            const float* hin = mod ? g_h2[t & 1] : g_h1[t & 1];
            float* hout = mod ? g_h2[(t & 1) ^ 1] : g_h1[(t & 1) ^ 1];
            const float* xg = xgb + (size_t)t * B_SZ * 256;

            // group A: h. group B: xg (waits deferred past MMA)
#pragma unroll
            for (int j = 0; j < 4; j++) {
                int id = tid + j * 256;
                int r = id >> 4, c = id & 15;
                cpasync16cg(&hs[r * 72 + c * 4], &hin[(rowBase + r) * 64 + c * 4]);
            }
            CP_COMMIT;
#pragma unroll
            for (int j = 0; j < 16; j++) {
                int id = tid + j * 256;
                int r = id >> 6, c = id & 63;
                cpasync16(&xbuf[r * 256 + c * 4],
                          &xg[(size_t)(rowBase + r) * 256 + c * 4]);
            }
            CP_COMMIT;
            CP_WAIT1;
            __syncthreads();

            float acc[2][8][4];
#pragma unroll
            for (int i = 0; i < 2; i++)
#pragma unroll
                for (int j = 0; j < 8; j++)
#pragma unroll
                    for (int v = 0; v < 4; v++) acc[i][j][v] = 0.0f;

#pragma unroll
            for (int kk = 0; kk < 8; kk++) {
                uint32_t a[2][4];
#pragma unroll
                for (int mt = 0; mt < 2; mt++) {
                    int ar = (wm * 32 + mt * 16 + gp) * 72 + kk * 8 + tg * 2;
                    float2 lo = *(float2*)&hs[ar];
                    float2 hi = *(float2*)&hs[ar + 8 * 72];
                    a[mt][0] = __float_as_uint(lo.x);
                    a[mt][1] = __float_as_uint(hi.x);
                    a[mt][2] = __float_as_uint(lo.y);
                    a[mt][3] = __float_as_uint(hi.y);
                }
#pragma unroll
                for (int nt = 0; nt < 8; nt++) {
                    int br = (wn * 64 + nt * 8 + gp) * 72 + kk * 8 + tg * 2;
                    float2 bv = *(float2*)&ws[br];
                    uint32_t b[2] = {__float_as_uint(bv.x), __float_as_uint(bv.y)};
#pragma unroll
                    for (int mt = 0; mt < 2; mt++) mma_tf32(acc[mt][nt], a[mt], b);
                }
            }

#pragma unroll
            for (int mt = 0; mt < 2; mt++)
#pragma unroll
                for (int nt = 0; nt < 8; nt++) {
                    int r = wm * 32 + mt * 16 + gp;
                    int col = wn * 64 + nt * 8 + 2 * tg;
                    *(float2*)&gsm[r * 256 + col] = make_float2(acc[mt][nt][0], acc[mt][nt][1]);
                    *(float2*)&gsm[(r + 8) * 256 + col] = make_float2(acc[mt][nt][2], acc[mt][nt][3]);
                }
            CP_WAIT0;
            __syncthreads();

            for (int idx = tid; idx < 4096; idx += 256) {
                int kl = idx & 63, bl = idx >> 6;
                float4 gt = *(float4*)&gsm[bl * 256 + 4 * kl];
                int bg = rowBase + bl;
                float4 xv = *(float4*)&xbuf[bl * 256 + 4 * kl];
                float ii = sigm(gt.x + xv.x);
                float ff = sigm(gt.y + xv.y);
                float gg = tanhfast(gt.z + xv.z);
                float oo = sigm(gt.w + xv.w);
                float cold = cb[bg * 64 + kl];
                float cn = ff * cold + ii * gg;
                float hn = oo * tanhfast(cn);
                cb[bg * 64 + kl] = cn;
                hout[bg * 64 + swz(kl)] = tf32r(hn);
            }
            __syncthreads();
        }
    }
}

// ---------------- launch 5: head ----------------
__global__ void head_kernel(const float* __restrict__ w1, const float* __restrict__ b1,
                            const float* __restrict__ w2, const float* __restrict__ b2,
                            float* __restrict__ out) {
    __shared__ float hc[8 * 384];
    __shared__ float red[256];
    int tid = threadIdx.x;
    int rowBase = blockIdx.x * 8;

    for (int i = tid; i < 8 * 384; i += 256) {
        int r = i / 384, d = i - r * 384;
        int bg = rowBase + r;
        float v;
        if (d < 256)      v = g_h0[0][bg * 256 + swz(d)];
        else if (d < 320) v = g_h1[0][bg * 64 + swz(d - 256)];
        else              v = g_h2[0][bg * 64 + swz(d - 320)];
        hc[i] = v;
    }
    __syncthreads();

    for (int pass = 0; pass < 2; pass++) {
        int row = pass * 4 + (tid >> 6);
        int cell = tid & 63;
        const float* wr = w1 + cell * 384;
        const float* hr = hc + row * 384;
        float a = b1[cell];
#pragma unroll 4
        for (int d = 0; d < 384; d++) a += hr[d] * wr[d];
        a = fmaxf(a, 0.0f);
        red[tid] = a * w2[cell];
        __syncthreads();
        if (cell == 0) {
            float s = 0.0f;
#pragma unroll
            for (int j = 0; j < 64; j++) s += red[tid + j];
            out[rowBase + row] = s + b2[0];
        }
        __syncthreads();
    }
}

// ---------------- launch ----------------
extern "C" void kernel_launch(void* const* d_in, const int* in_sizes, int n_in,
                              void* d_out, int out_size) {
    const float* x0    = (const float*)d_in[0];
    const float* x1    = (const float*)d_in[1];
    const float* x2    = (const float*)d_in[2];
    const float* w_ih0 = (const float*)d_in[3];
    const float* w_hh0 = (const float*)d_in[4];
    const float* b_ih0 = (const float*)d_in[5];
    const float* b_hh0 = (const float*)d_in[6];
    const float* w_ih1 = (const float*)d_in[7];
    const float* w_hh1 = (const float*)d_in[8];
    const float* b_ih1 = (const float*)d_in[9];
    const float* b_hh1 = (const float*)d_in[10];
    const float* w_ih2 = (const float*)d_in[11];
    const float* w_hh2 = (const float*)d_in[12];
    const float* b_ih2 = (const float*)d_in[13];
    const float* b_hh2 = (const float*)d_in[14];
    const float* w1    = (const float*)d_in[15];
    const float* b1    = (const float*)d_in[16];
    const float* w2    = (const float*)d_in[17];
    const float* b2    = (const float*)d_in[18];
    float* out = (float*)d_out;

    cudaFuncSetAttribute(persist_kernel, cudaFuncAttributeMaxDynamicSharedMemorySize,
                         SMEM_PERSIST);
    cudaFuncSetAttribute(proj_all_kernel, cudaFuncAttributeMaxDynamicSharedMemorySize,
                         SMEM_PROJ);

    // launch 0
    prep_w_kernel<<<512, 256>>>(w_ih0, w_hh0, b_ih0, b_hh0,
                                w_ih1, w_hh1, b_ih1, b_hh1,
                                w_ih2, w_hh2, b_ih2, b_hh2);
    // launch 1
    prep_x_kernel<<<1024, 256>>>(x0, x1, x2);
    // launch 2
    init_kernel<<<256, 256>>>();
    // launch 3  (ncu capture index) — the projection GEMM
    proj_all_kernel<<<dim3(6, 512), 256, SMEM_PROJ>>>();
    // launch 4
    persist_kernel<<<NBLK, 256, SMEM_PERSIST>>>();
    // launch 5
    head_kernel<<<64, 256>>>(w1, b1, w2, b2, out);
}

// round 7
// speedup vs baseline: 1.1262x; 1.1262x over previous
#include <cuda_runtime.h>
#include <cstdint>

#define B_SZ 512
#define T_SZ 128
#define NBLK 144
#define SMEM_PERSIST 223360
#define SMEM_PROJ    92288

// ---------------- __device__ scratch (no allocations allowed) ----------------
// xg0: [t][bn(8)][b(512)][128]
__device__ __align__(128) float g_xg0[(size_t)T_SZ * 8 * B_SZ * 128];
__device__ __align__(128) float g_xg1[(size_t)T_SZ * B_SZ * 256];
__device__ __align__(128) float g_xg2[(size_t)T_SZ * B_SZ * 256];
// xp: [kt][row(65536)][20]  (16 swizzled k-values + 4 pad)
__device__ __align__(128) float g_xp0[(size_t)19 * 65536 * 20];
__device__ __align__(128) float g_xp1[(size_t)5 * 65536 * 20];
__device__ __align__(128) float g_xp2[(size_t)3 * 65536 * 20];
// wih: [kt][gate][20]
__device__ __align__(128) float g_wih0[19 * 1024 * 20];
__device__ __align__(128) float g_wih1[5 * 256 * 20];
__device__ __align__(128) float g_wih2[3 * 256 * 20];
__device__ __align__(128) float g_whh0[1024 * 256];   // [gate][256], K pair-swizzled
__device__ __align__(128) float g_whh1[256 * 64];
__device__ __align__(128) float g_whh2[256 * 64];
__device__ __align__(128) float g_bias0[1024];
__device__ __align__(128) float g_bias1[256];
__device__ __align__(128) float g_bias2[256];
// h: row-padded so a tile is ONE contiguous bulk copy landing bank-conflict-free
__device__ __align__(128) float g_h0[2][B_SZ * 264];  // stride 264, tf32, pair-swizzled
__device__ __align__(128) float g_h1[2][B_SZ * 72];   // stride 72
__device__ __align__(128) float g_h2[2][B_SZ * 72];
__device__ __align__(128) float g_c1[B_SZ * 64];
__device__ __align__(128) float g_c2[B_SZ * 64];
__device__ __align__(128) unsigned g_bar0[16 * 32];

// ---------------- helpers ----------------
__device__ __forceinline__ int swz(int k) {
    return (k & ~7) | ((k & 3) << 1) | ((k >> 2) & 1);
}

__device__ __forceinline__ float tf32r(float x) {
    uint32_t u;
    asm("cvt.rna.tf32.f32 %0, %1;" : "=r"(u) : "f"(x));
    return __uint_as_float(u);
}

__device__ __forceinline__ void mma_tf32(float c[4], const uint32_t a[4], const uint32_t b[2]) {
    asm volatile(
        "mma.sync.aligned.m16n8k8.row.col.f32.tf32.tf32.f32 "
        "{%0,%1,%2,%3}, {%4,%5,%6,%7}, {%8,%9}, {%0,%1,%2,%3};"
        : "+f"(c[0]), "+f"(c[1]), "+f"(c[2]), "+f"(c[3])
        : "r"(a[0]), "r"(a[1]), "r"(a[2]), "r"(a[3]), "r"(b[0]), "r"(b[1]));
}

__device__ __forceinline__ float fex2(float x) {
    float r; asm("ex2.approx.f32 %0, %1;" : "=f"(r) : "f"(x)); return r;
}
__device__ __forceinline__ float frcp(float x) {
    float r; asm("rcp.approx.f32 %0, %1;" : "=f"(r) : "f"(x)); return r;
}
__device__ __forceinline__ float sigm(float x) {
    return frcp(1.0f + fex2(-1.4426950408889634f * x));
}
__device__ __forceinline__ float tanhfast(float x) {
    return 2.0f * frcp(1.0f + fex2(-2.8853900817779268f * x)) - 1.0f;
}

// ---- bulk-copy + mbarrier primitives ----
__device__ __forceinline__ uint32_t s2u(const void* p) {
    return (uint32_t)__cvta_generic_to_shared(p);
}
__device__ __forceinline__ void mbar_init(uint32_t mb, uint32_t cnt) {
    asm volatile("mbarrier.init.shared.b64 [%0], %1;" :: "r"(mb), "r"(cnt) : "memory");
}
__device__ __forceinline__ void mbar_arrive_tx(uint32_t mb, uint32_t bytes) {
    asm volatile("mbarrier.arrive.expect_tx.shared.b64 _, [%0], %1;"
                 :: "r"(mb), "r"(bytes) : "memory");
}
__device__ __forceinline__ void mbar_wait(uint32_t mb, uint32_t parity) {
    asm volatile(
        "{\n\t.reg .pred P;\n"
        "W%=:\n\t"
        "mbarrier.try_wait.parity.shared.b64 P, [%0], %1;\n\t"
        "@!P bra W%=;\n\t}"
        :: "r"(mb), "r"(parity) : "memory");
}
__device__ __forceinline__ void bulk_g2s(uint32_t dst, const void* src,
                                         uint32_t bytes, uint32_t mb) {
    asm volatile(
        "cp.async.bulk.shared::cluster.global.mbarrier::complete_tx::bytes "
        "[%0], [%1], %2, [%3];"
        :: "r"(dst), "l"(src), "r"(bytes), "r"(mb) : "memory");
}
#define FENCE_ASYNC asm volatile("fence.proxy.async.shared::cta;" ::: "memory")

// ---------------- launch 0: prep weights ----------------
__global__ void prep_w_kernel(
    const float* __restrict__ wih0, const float* __restrict__ whh0,
    const float* __restrict__ bih0, const float* __restrict__ bhh0,
    const float* __restrict__ wih1, const float* __restrict__ whh1,
    const float* __restrict__ bih1, const float* __restrict__ bhh1,
    const float* __restrict__ wih2, const float* __restrict__ whh2,
    const float* __restrict__ bih2, const float* __restrict__ bhh2)
{
    size_t stride = (size_t)gridDim.x * blockDim.x;
    size_t t0 = (size_t)blockIdx.x * blockDim.x + threadIdx.x;

    // wih -> [kt][gate'][20], gate-interleaved rows g' = 4k+q, within-16 swizzle
    for (size_t ii = t0; ii < 1024 * 304; ii += stride) {
        int i = (int)ii;
        int gp = i / 304, dp = i - gp * 304;
        int k = gp >> 2, q = gp & 3, go = q * 256 + k;
        g_wih0[((size_t)(dp >> 4) * 1024 + gp) * 20 + swz(dp & 15)] =
            (dp < 300) ? tf32r(wih0[go * 300 + dp]) : 0.0f;
    }
    for (size_t ii = t0; ii < 256 * 80; ii += stride) {
        int i = (int)ii;
        int gp = i / 80, dp = i - gp * 80;
        int k = gp >> 2, q = gp & 3, go = q * 64 + k;
        g_wih1[((size_t)(dp >> 4) * 256 + gp) * 20 + swz(dp & 15)] =
            (dp < 74) ? tf32r(wih1[go * 74 + dp]) : 0.0f;
    }
    for (size_t ii = t0; ii < 256 * 48; ii += stride) {
        int i = (int)ii;
        int gp = i / 48, dp = i - gp * 48;
        int k = gp >> 2, q = gp & 3, go = q * 64 + k;
        g_wih2[((size_t)(dp >> 4) * 256 + gp) * 20 + swz(dp & 15)] =
            (dp < 35) ? tf32r(wih2[go * 35 + dp]) : 0.0f;
    }
    // whh (unchanged layout)
    for (size_t ii = t0; ii < 1024 * 256; ii += stride) {
        int i = (int)ii;
        int gp = i >> 8, dp = i & 255;
        int k = gp >> 2, q = gp & 3, go = q * 256 + k;
        g_whh0[gp * 256 + swz(dp)] = tf32r(whh0[go * 256 + dp]);
    }
    for (size_t ii = t0; ii < 256 * 64; ii += stride) {
        int i = (int)ii;
        int gp = i >> 6, dp = i & 63;
        int k = gp >> 2, q = gp & 3, go = q * 64 + k;
        g_whh1[gp * 64 + swz(dp)] = tf32r(whh1[go * 64 + dp]);
        g_whh2[gp * 64 + swz(dp)] = tf32r(whh2[go * 64 + dp]);
    }
    for (size_t ii = t0; ii < 1024; ii += stride) {
        int i = (int)ii;
        int k = i >> 2, q = i & 3, go = q * 256 + k;
        g_bias0[i] = bih0[go] + bhh0[go];
    }
    for (size_t ii = t0; ii < 256; ii += stride) {
        int i = (int)ii;
        int k = i >> 2, q = i & 3, go = q * 64 + k;
        g_bias1[i] = bih1[go] + bhh1[go];
        g_bias2[i] = bih2[go] + bhh2[go];
    }
}

// ---------------- launch 1: pad x -> xp [kt][row][20] ----------------
__global__ void prep_x_kernel(
    const float* __restrict__ x0, const float* __restrict__ x1, const float* __restrict__ x2)
{
    size_t stride = (size_t)gridDim.x * blockDim.x;
    size_t t0 = (size_t)blockIdx.x * blockDim.x + threadIdx.x;

    for (size_t i = t0; i < (size_t)65536 * 304; i += stride) {
        int r = (int)(i / 304), d = (int)(i - (size_t)r * 304);
        g_xp0[((size_t)(d >> 4) * 65536 + r) * 20 + swz(d & 15)] =
            (d < 300) ? tf32r(x0[(size_t)r * 300 + d]) : 0.0f;
    }
    for (size_t i = t0; i < (size_t)65536 * 80; i += stride) {
        int r = (int)(i / 80), d = (int)(i - (size_t)r * 80);
        g_xp1[((size_t)(d >> 4) * 65536 + r) * 20 + swz(d & 15)] =
            (d < 74) ? tf32r(x1[(size_t)r * 74 + d]) : 0.0f;
    }
    for (size_t i = t0; i < (size_t)65536 * 48; i += stride) {
        int r = (int)(i / 48), d = (int)(i - (size_t)r * 48);
        g_xp2[((size_t)(d >> 4) * 65536 + r) * 20 + swz(d & 15)] =
            (d < 35) ? tf32r(x2[(size_t)r * 35 + d]) : 0.0f;
    }
}

// ---------------- launch 2: init ----------------
__global__ void init_kernel() {
    int stride = gridDim.x * blockDim.x;
    int i0 = blockIdx.x * blockDim.x + threadIdx.x;
    for (int i = i0; i < 16 * 32; i += stride) g_bar0[i] = 0u;
    for (int i = i0; i < B_SZ * 264; i += stride) g_h0[0][i] = 0.0f;
    for (int i = i0; i < B_SZ * 72; i += stride) { g_h1[0][i] = 0.0f; g_h2[0][i] = 0.0f; }
    for (int i = i0; i < B_SZ * 64; i += stride) { g_c1[i] = 0.0f; g_c2[i] = 0.0f; }
}

// ---------------- launch 3: projections, 128x256 tiles, 3-stage bulk pipeline ------
__device__ __forceinline__ void proj_impl(
    const float* __restrict__ XP, const float* __restrict__ W,
    const float* __restrict__ bias, float* __restrict__ XG,
    int G, int KT, int colBase, int rowBase, float* psm)
{
    int tid = threadIdx.x, lane = tid & 31, warp = tid >> 5;
    int gp = lane >> 2, tg = lane & 3;
    int wm = warp >> 1, wn = warp & 1; // 4m x 2n warps; warp tile 32 x 128

    uint32_t mb = s2u(psm);       // 3 mbarriers (8B each)
    float* buf = psm + 32;        // stage s: x[128x20] then w[256x20]

    if (tid == 0) {
        mbar_init(mb, 1); mbar_init(mb + 8, 1); mbar_init(mb + 16, 1);
        FENCE_ASYNC;
    }
    __syncthreads();

    float acc[2][16][4];
#pragma unroll
    for (int i = 0; i < 2; i++)
#pragma unroll
        for (int j = 0; j < 16; j++)
#pragma unroll
            for (int v = 0; v < 4; v++) acc[i][j][v] = 0.0f;

    auto issue = [&](int kt, int s) {
        if (tid == 0) {
            float* xd = buf + s * 7680;
            float* wd = xd + 2560;
            uint32_t m = mb + 8u * s;
            mbar_arrive_tx(m, 30720);
            bulk_g2s(s2u(xd), XP + ((size_t)kt * 65536 + rowBase) * 20, 10240, m);
            bulk_g2s(s2u(wd), W + ((size_t)kt * G + colBase) * 20, 20480, m);
        }
    };

    issue(0, 0);
    issue(1, 1);

    for (int kt = 0; kt < KT; kt++) {
        int s = kt % 3;
        mbar_wait(mb + 8u * s, (uint32_t)((kt / 3) & 1));
        float* xb = buf + s * 7680;
        float* wb = xb + 2560;
#pragma unroll
        for (int kk = 0; kk < 2; kk++) {
            uint32_t a[2][4];
#pragma unroll
            for (int mt = 0; mt < 2; mt++) {
                int ar = (wm * 32 + mt * 16 + gp) * 20 + kk * 8 + tg * 2;
                float2 lo = *(float2*)&xb[ar];
                float2 hi = *(float2*)&xb[ar + 160];
                a[mt][0] = __float_as_uint(lo.x);
                a[mt][1] = __float_as_uint(hi.x);
                a[mt][2] = __float_as_uint(lo.y);
                a[mt][3] = __float_as_uint(hi.y);
            }
#pragma unroll
            for (int nt = 0; nt < 16; nt++) {
                int br = (wn * 128 + nt * 8 + gp) * 20 + kk * 8 + tg * 2;
                float2 bv = *(float2*)&wb[br];
                uint32_t b[2] = {__float_as_uint(bv.x), __float_as_uint(bv.y)};
#pragma unroll
                for (int mt = 0; mt < 2; mt++) mma_tf32(acc[mt][nt], a[mt], b);
            }
        }
        __syncthreads();                 // all threads done with stage (kt-1)%3 region
        if (kt + 2 < KT) issue(kt + 2, (kt + 2) % 3);
    }

#pragma unroll
    for (int mt = 0; mt < 2; mt++)
#pragma unroll
        for (int nt = 0; nt < 16; nt++) {
            int r0 = rowBase + wm * 32 + mt * 16 + gp;
            int col = colBase + wn * 128 + nt * 8 + 2 * tg;
            float bx = bias[col], by = bias[col + 1];
            int tt0 = r0 & 127, bb0 = r0 >> 7;
            int r1 = r0 + 8;
            int tt1 = r1 & 127, bb1 = r1 >> 7;
            size_t o0, o1;
            if (G == 1024) {
                int bnn = col >> 7, cl = col & 127;
                o0 = (((size_t)tt0 * 8 + bnn) * B_SZ + bb0) * 128 + cl;
                o1 = (((size_t)tt1 * 8 + bnn) * B_SZ + bb1) * 128 + cl;
            } else {
                o0 = ((size_t)tt0 * B_SZ + bb0) * 256 + col;
                o1 = ((size_t)tt1 * B_SZ + bb1) * 256 + col;
            }
            *(float2*)&XG[o0] = make_float2(acc[mt][nt][0] + bx, acc[mt][nt][1] + by);
            *(float2*)&XG[o1] = make_float2(acc[mt][nt][2] + bx, acc[mt][nt][3] + by);
        }
}

__global__ __launch_bounds__(256) void proj_all_kernel() {
    extern __shared__ __align__(16) float psm[];
    int bx = blockIdx.x;
    int rowBase = blockIdx.y * 128;
    if (bx < 4) {
        proj_impl(g_xp0, g_wih0, g_bias0, g_xg0, 1024, 19, bx * 256, rowBase, psm);
    } else if (bx == 4) {
        proj_impl(g_xp1, g_wih1, g_bias1, g_xg1, 256, 5, 0, rowBase, psm);
    } else {
        proj_impl(g_xp2, g_wih2, g_bias2, g_xg2, 256, 3, 0, rowBase, psm);
    }
}

// ---------------- launch 4: persistent recurrence ----------------
__global__ __launch_bounds__(256, 1) void persist_kernel() {
    extern __shared__ __align__(16) float sm[];
    int bid = blockIdx.x, tid = threadIdx.x;
    int lane = tid & 31, warp = tid >> 5;
    int gp = lane >> 2, tg = lane & 3;

    if (bid < 128) {
        // ================= module 0: H=256, G=1024 =================
        int bm = bid >> 3, bn = bid & 7;
        int rowBase = bm * 32, colBase = bn * 128;
        float* hs   = sm + 32;         // 32 x 264
        float* xbuf = hs + 8448;       // 32 x 128
        float* gsm  = xbuf + 4096;     // 32 x 128
        uint32_t mb_h = s2u(sm);
        uint32_t mb_x = mb_h + 8;

        if (tid == 0) { mbar_init(mb_h, 1); mbar_init(mb_x, 1); FENCE_ASYNC; }
        __syncthreads();

        // weights in registers: warp wn owns cols [wn*16, wn*16+16), all K
        int wn = warp;
        uint32_t breg[32][2][2];
#pragma unroll
        for (int kk = 0; kk < 32; kk++)
#pragma unroll
            for (int nt = 0; nt < 2; nt++) {
                float2 v = *(const float2*)
                    &g_whh0[(size_t)(colBase + wn * 16 + nt * 8 + gp) * 256 + kk * 8 + tg * 2];
                breg[kk][nt][0] = __float_as_uint(v.x);
                breg[kk][nt][1] = __float_as_uint(v.y);
            }

        float creg[4] = {0.0f, 0.0f, 0.0f, 0.0f};
        unsigned* cnt = &g_bar0[bm * 32];

        for (int t = 0; t < T_SZ; t++) {
            const float* hin = g_h0[t & 1];
            float* hout = g_h0[(t & 1) ^ 1];

            if (tid == 0) {
                mbar_arrive_tx(mb_h, 33792);
                bulk_g2s(s2u(hs), hin + rowBase * 264, 33792, mb_h);
                mbar_arrive_tx(mb_x, 16384);
                bulk_g2s(s2u(xbuf),
                         g_xg0 + (((size_t)t * 8 + bn) * B_SZ + rowBase) * 128,
                         16384, mb_x);
            }
            mbar_wait(mb_h, (uint32_t)(t & 1));

            float acc[2][2][4];
#pragma unroll
            for (int i = 0; i < 2; i++)
#pragma unroll
                for (int j = 0; j < 2; j++)
#pragma unroll
                    for (int v = 0; v < 4; v++) acc[i][j][v] = 0.0f;

#pragma unroll
            for (int kk = 0; kk < 32; kk++) {
                int kb = kk * 8 + tg * 2;
                float2 lo0 = *(float2*)&hs[gp * 264 + kb];
                float2 hi0 = *(float2*)&hs[(gp + 8) * 264 + kb];
                float2 lo1 = *(float2*)&hs[(gp + 16) * 264 + kb];
                float2 hi1 = *(float2*)&hs[(gp + 24) * 264 + kb];
                uint32_t a0[4] = {__float_as_uint(lo0.x), __float_as_uint(hi0.x),
                                  __float_as_uint(lo0.y), __float_as_uint(hi0.y)};
                uint32_t a1[4] = {__float_as_uint(lo1.x), __float_as_uint(hi1.x),
                                  __float_as_uint(lo1.y), __float_as_uint(hi1.y)};
                mma_tf32(acc[0][0], a0, breg[kk][0]);
                mma_tf32(acc[0][1], a0, breg[kk][1]);
                mma_tf32(acc[1][0], a1, breg[kk][0]);
                mma_tf32(acc[1][1], a1, breg[kk][1]);
            }

#pragma unroll
            for (int mt = 0; mt < 2; mt++)
#pragma unroll
                for (int nt = 0; nt < 2; nt++) {
                    int r = mt * 16 + gp, col = wn * 16 + nt * 8 + tg * 2;
                    *(float2*)&gsm[r * 128 + col] =
                        make_float2(acc[mt][nt][0], acc[mt][nt][1]);
                    *(float2*)&gsm[(r + 8) * 128 + col] =
                        make_float2(acc[mt][nt][2], acc[mt][nt][3]);
                }
            __syncthreads();
            mbar_wait(mb_x, (uint32_t)(t & 1));

#pragma unroll
            for (int j = 0; j < 4; j++) {
                int idx = tid + j * 256;
                int bl = idx >> 5, kl = idx & 31;
                float4 gt = *(float4*)&gsm[bl * 128 + 4 * kl];
                float4 xv = *(float4*)&xbuf[bl * 128 + 4 * kl];
                float ii = sigm(gt.x + xv.x);
                float ff = sigm(gt.y + xv.y);
                float gg = tanhfast(gt.z + xv.z);
                float oo = sigm(gt.w + xv.w);
                float cn = ff * creg[j] + ii * gg;
                creg[j] = cn;
                float hn = oo * tanhfast(cn);
                hout[(rowBase + bl) * 264 + swz(bn * 32 + kl)] = tf32r(hn);
            }

            if (t + 1 < T_SZ) {
                __syncthreads();
                if (tid == 0) {
                    __threadfence();
                    atomicAdd(cnt, 1u);
                    unsigned tgt = 8u * (unsigned)(t + 1);
                    while (*(volatile unsigned*)cnt < tgt) {}
                    __threadfence();
                }
                __syncthreads();
            }
        }
    } else {
        // ================= modules 1,2: H=64, G=256, fully independent ============
        int sub = bid - 128;
        int mod = sub >> 3, bm = sub & 7;
        int rowBase = bm * 64;
        const float* whh = mod ? g_whh2 : g_whh1;
        const float* xgb = mod ? g_xg2 : g_xg1;
        float* cb = mod ? g_c2 : g_c1;

        float* ws   = sm + 32;         // 256 x 72
        float* hs   = ws + 18432;      // 64 x 72
        float* gsm  = hs + 4608;       // 64 x 256
        float* xbuf = gsm + 16384;     // 64 x 256
        uint32_t mb_h = s2u(sm);
        uint32_t mb_x = mb_h + 8;

        if (tid == 0) { mbar_init(mb_h, 1); mbar_init(mb_x, 1); FENCE_ASYNC; }
        __syncthreads();

        for (int idx = tid; idx < 256 * 16; idx += 256) {
            int r = idx >> 4, c = idx & 15;
            *(float4*)&ws[r * 72 + c * 4] = *(const float4*)&whh[r * 64 + c * 4];
        }
        __syncthreads();

        int wm = warp >> 2, wn = warp & 3;

        for (int t = 0; t < T_SZ; t++) {
            const float* hin = mod ? g_h2[t & 1] : g_h1[t & 1];
            float* hout = mod ? g_h2[(t & 1) ^ 1] : g_h1[(t & 1) ^ 1];

            if (tid == 0) {
                mbar_arrive_tx(mb_h, 18432);
                bulk_g2s(s2u(hs), hin + rowBase * 72, 18432, mb_h);
                mbar_arrive_tx(mb_x, 65536);
                bulk_g2s(s2u(xbuf),
                         xgb + ((size_t)t * B_SZ + rowBase) * 256, 65536, mb_x);
            }
            mbar_wait(mb_h, (uint32_t)(t & 1));

            float acc[2][8][4];
#pragma unroll
            for (int i = 0; i < 2; i++)
#pragma unroll
                for (int j = 0; j < 8; j++)
#pragma unroll
                    for (int v = 0; v < 4; v++) acc[i][j][v] = 0.0f;

#pragma unroll
            for (int kk = 0; kk < 8; kk++) {
                uint32_t a[2][4];
#pragma unroll
                for (int mt = 0; mt < 2; mt++) {
                    int ar = (wm * 32 + mt * 16 + gp) * 72 + kk * 8 + tg * 2;
                    float2 lo = *(float2*)&hs[ar];
                    float2 hi = *(float2*)&hs[ar + 576];
                    a[mt][0] = __float_as_uint(lo.x);
                    a[mt][1] = __float_as_uint(hi.x);
                    a[mt][2] = __float_as_uint(lo.y);
                    a[mt][3] = __float_as_uint(hi.y);
                }
#pragma unroll
                for (int nt = 0; nt < 8; nt++) {
                    int br = (wn * 64 + nt * 8 + gp) * 72 + kk * 8 + tg * 2;
                    float2 bv = *(float2*)&ws[br];
                    uint32_t b[2] = {__float_as_uint(bv.x), __float_as_uint(bv.y)};
#pragma unroll
                    for (int mt = 0; mt < 2; mt++) mma_tf32(acc[mt][nt], a[mt], b);
                }
            }

#pragma unroll
            for (int mt = 0; mt < 2; mt++)
#pragma unroll
                for (int nt = 0; nt < 8; nt++) {
                    int r = wm * 32 + mt * 16 + gp;
                    int col = wn * 64 + nt * 8 + 2 * tg;
                    *(float2*)&gsm[r * 256 + col] = make_float2(acc[mt][nt][0], acc[mt][nt][1]);
                    *(float2*)&gsm[(r + 8) * 256 + col] = make_float2(acc[mt][nt][2], acc[mt][nt][3]);
                }
            __syncthreads();
            mbar_wait(mb_x, (uint32_t)(t & 1));

            for (int idx = tid; idx < 4096; idx += 256) {
                int kl = idx & 63, bl = idx >> 6;
                float4 gt = *(float4*)&gsm[bl * 256 + 4 * kl];
                int bg = rowBase + bl;
                float4 xv = *(float4*)&xbuf[bl * 256 + 4 * kl];
                float ii = sigm(gt.x + xv.x);
                float ff = sigm(gt.y + xv.y);
                float gg = tanhfast(gt.z + xv.z);
                float oo = sigm(gt.w + xv.w);
                float cold = cb[bg * 64 + kl];
                float cn = ff * cold + ii * gg;
                float hn = oo * tanhfast(cn);
                cb[bg * 64 + kl] = cn;
                hout[bg * 72 + swz(kl)] = tf32r(hn);
            }
            __syncthreads();
        }
    }
}

// ---------------- launch 5: head ----------------
__global__ void head_kernel(const float* __restrict__ w1, const float* __restrict__ b1,
                            const float* __restrict__ w2, const float* __restrict__ b2,
                            float* __restrict__ out) {
    __shared__ float hc[8 * 384];
    __shared__ float red[256];
    int tid = threadIdx.x;
    int rowBase = blockIdx.x * 8;

    for (int i = tid; i < 8 * 384; i += 256) {
        int r = i / 384, d = i - r * 384;
        int bg = rowBase + r;
        float v;
        if (d < 256)      v = g_h0[0][bg * 264 + swz(d)];
        else if (d < 320) v = g_h1[0][bg * 72 + swz(d - 256)];
        else              v = g_h2[0][bg * 72 + swz(d - 320)];
        hc[i] = v;
    }
    __syncthreads();

    for (int pass = 0; pass < 2; pass++) {
        int row = pass * 4 + (tid >> 6);
        int cell = tid & 63;
        const float* wr = w1 + cell * 384;
        const float* hr = hc + row * 384;
        float a = b1[cell];
#pragma unroll 4
        for (int d = 0; d < 384; d++) a += hr[d] * wr[d];
        a = fmaxf(a, 0.0f);
        red[tid] = a * w2[cell];
        __syncthreads();
        if (cell == 0) {
            float s = 0.0f;
#pragma unroll
            for (int j = 0; j < 64; j++) s += red[tid + j];
            out[rowBase + row] = s + b2[0];
        }
        __syncthreads();
    }
}

// ---------------- launch ----------------
extern "C" void kernel_launch(void* const* d_in, const int* in_sizes, int n_in,
                              void* d_out, int out_size) {
    const float* x0    = (const float*)d_in[0];
    const float* x1    = (const float*)d_in[1];
    const float* x2    = (const float*)d_in[2];
    const float* w_ih0 = (const float*)d_in[3];
    const float* w_hh0 = (const float*)d_in[4];
    const float* b_ih0 = (const float*)d_in[5];
    const float* b_hh0 = (const float*)d_in[6];
    const float* w_ih1 = (const float*)d_in[7];
    const float* w_hh1 = (const float*)d_in[8];
    const float* b_ih1 = (const float*)d_in[9];
    const float* b_hh1 = (const float*)d_in[10];
    const float* w_ih2 = (const float*)d_in[11];
    const float* w_hh2 = (const float*)d_in[12];
    const float* b_ih2 = (const float*)d_in[13];
    const float* b_hh2 = (const float*)d_in[14];
    const float* w1    = (const float*)d_in[15];
    const float* b1    = (const float*)d_in[16];
    const float* w2    = (const float*)d_in[17];
    const float* b2    = (const float*)d_in[18];
    float* out = (float*)d_out;

    cudaFuncSetAttribute(persist_kernel, cudaFuncAttributeMaxDynamicSharedMemorySize,
                         SMEM_PERSIST);
    cudaFuncSetAttribute(proj_all_kernel, cudaFuncAttributeMaxDynamicSharedMemorySize,
                         SMEM_PROJ);

    // launch 0
    prep_w_kernel<<<512, 256>>>(w_ih0, w_hh0, b_ih0, b_hh0,
                                w_ih1, w_hh1, b_ih1, b_hh1,
                                w_ih2, w_hh2, b_ih2, b_hh2);
    // launch 1
    prep_x_kernel<<<1024, 256>>>(x0, x1, x2);
    // launch 2
    init_kernel<<<256, 256>>>();
    // launch 3  (ncu capture index) — the projection GEMM
    proj_all_kernel<<<dim3(6, 512), 256, SMEM_PROJ>>>();
    // launch 4
    persist_kernel<<<NBLK, 256, SMEM_PERSIST>>>();
    // launch 5
    head_kernel<<<64, 256>>>(w1, b1, w2, b2, out);
}

// round 8
// speedup vs baseline: 1.1293x; 1.0028x over previous
#include <cuda_runtime.h>
#include <cstdint>

#define B_SZ 512
#define T_SZ 128
#define NBLK 144
#define SMEM_PERSIST 223360
#define SMEM_PROJ    92288

// ---------------- __device__ scratch (no allocations allowed) ----------------
// xg0: [t][bn(8)][b(512)][128]
__device__ __align__(128) float g_xg0[(size_t)T_SZ * 8 * B_SZ * 128];
__device__ __align__(128) float g_xg1[(size_t)T_SZ * B_SZ * 256];
__device__ __align__(128) float g_xg2[(size_t)T_SZ * B_SZ * 256];
// xp: [kt][row(65536)][20]  (16 swizzled k-values + 4 pad)
__device__ __align__(128) float g_xp0[(size_t)19 * 65536 * 20];
__device__ __align__(128) float g_xp1[(size_t)5 * 65536 * 20];
__device__ __align__(128) float g_xp2[(size_t)3 * 65536 * 20];
// wih: [kt][gate][20]
__device__ __align__(128) float g_wih0[19 * 1024 * 20];
__device__ __align__(128) float g_wih1[5 * 256 * 20];
__device__ __align__(128) float g_wih2[3 * 256 * 20];
__device__ __align__(128) float g_whh0[1024 * 256];   // [gate][256], K pair-swizzled
__device__ __align__(128) float g_whh1[256 * 64];
__device__ __align__(128) float g_whh2[256 * 64];
__device__ __align__(128) float g_bias0[1024];
__device__ __align__(128) float g_bias1[256];
__device__ __align__(128) float g_bias2[256];
// h: row-padded so a tile is ONE contiguous bulk copy landing bank-conflict-free
__device__ __align__(128) float g_h0[2][B_SZ * 264];  // stride 264, tf32, pair-swizzled
__device__ __align__(128) float g_h1[2][B_SZ * 72];   // stride 72
__device__ __align__(128) float g_h2[2][B_SZ * 72];
__device__ __align__(128) float g_c1[B_SZ * 64];
__device__ __align__(128) float g_c2[B_SZ * 64];
__device__ __align__(128) unsigned g_bar0[16 * 32];

// ---------------- helpers ----------------
__device__ __forceinline__ int swz(int k) {
    return (k & ~7) | ((k & 3) << 1) | ((k >> 2) & 1);
}

__device__ __forceinline__ float tf32r(float x) {
    uint32_t u;
    asm("cvt.rna.tf32.f32 %0, %1;" : "=r"(u) : "f"(x));
    return __uint_as_float(u);
}

__device__ __forceinline__ void mma_tf32(float c[4], const uint32_t a[4], const uint32_t b[2]) {
    asm volatile(
        "mma.sync.aligned.m16n8k8.row.col.f32.tf32.tf32.f32 "
        "{%0,%1,%2,%3}, {%4,%5,%6,%7}, {%8,%9}, {%0,%1,%2,%3};"
        : "+f"(c[0]), "+f"(c[1]), "+f"(c[2]), "+f"(c[3])
        : "r"(a[0]), "r"(a[1]), "r"(a[2]), "r"(a[3]), "r"(b[0]), "r"(b[1]));
}

__device__ __forceinline__ float fex2(float x) {
    float r; asm("ex2.approx.f32 %0, %1;" : "=f"(r) : "f"(x)); return r;
}
__device__ __forceinline__ float frcp(float x) {
    float r; asm("rcp.approx.f32 %0, %1;" : "=f"(r) : "f"(x)); return r;
}
__device__ __forceinline__ float sigm(float x) {
    return frcp(1.0f + fex2(-1.4426950408889634f * x));
}
__device__ __forceinline__ float tanhfast(float x) {
    return 2.0f * frcp(1.0f + fex2(-2.8853900817779268f * x)) - 1.0f;
}

// ---- bulk-copy + mbarrier primitives ----
__device__ __forceinline__ uint32_t s2u(const void* p) {
    return (uint32_t)__cvta_generic_to_shared(p);
}
__device__ __forceinline__ void mbar_init(uint32_t mb, uint32_t cnt) {
    asm volatile("mbarrier.init.shared.b64 [%0], %1;" :: "r"(mb), "r"(cnt) : "memory");
}
__device__ __forceinline__ void mbar_arrive_tx(uint32_t mb, uint32_t bytes) {
    asm volatile("mbarrier.arrive.expect_tx.shared.b64 _, [%0], %1;"
                 :: "r"(mb), "r"(bytes) : "memory");
}
__device__ __forceinline__ void mbar_wait(uint32_t mb, uint32_t parity) {
    asm volatile(
        "{\n\t.reg .pred P;\n"
        "W%=:\n\t"
        "mbarrier.try_wait.parity.shared.b64 P, [%0], %1;\n\t"
        "@!P bra W%=;\n\t}"
        :: "r"(mb), "r"(parity) : "memory");
}
__device__ __forceinline__ void bulk_g2s(uint32_t dst, const void* src,
                                         uint32_t bytes, uint32_t mb) {
    asm volatile(
        "cp.async.bulk.shared::cluster.global.mbarrier::complete_tx::bytes "
        "[%0], [%1], %2, [%3];"
        :: "r"(dst), "l"(src), "r"(bytes), "r"(mb) : "memory");
}
#define FENCE_ASYNC asm volatile("fence.proxy.async.shared::cta;" ::: "memory")

// ---------------- launch 0: prep weights ----------------
__global__ void prep_w_kernel(
    const float* __restrict__ wih0, const float* __restrict__ whh0,
    const float* __restrict__ bih0, const float* __restrict__ bhh0,
    const float* __restrict__ wih1, const float* __restrict__ whh1,
    const float* __restrict__ bih1, const float* __restrict__ bhh1,
    const float* __restrict__ wih2, const float* __restrict__ whh2,
    const float* __restrict__ bih2, const float* __restrict__ bhh2)
{
    size_t stride = (size_t)gridDim.x * blockDim.x;
    size_t t0 = (size_t)blockIdx.x * blockDim.x + threadIdx.x;

    // wih -> [kt][gate'][20], gate-interleaved rows g' = 4k+q, within-16 swizzle
    for (size_t ii = t0; ii < 1024 * 304; ii += stride) {
        int i = (int)ii;
        int gp = i / 304, dp = i - gp * 304;
        int k = gp >> 2, q = gp & 3, go = q * 256 + k;
        g_wih0[((size_t)(dp >> 4) * 1024 + gp) * 20 + swz(dp & 15)] =
            (dp < 300) ? tf32r(wih0[go * 300 + dp]) : 0.0f;
    }
    for (size_t ii = t0; ii < 256 * 80; ii += stride) {
        int i = (int)ii;
        int gp = i / 80, dp = i - gp * 80;
        int k = gp >> 2, q = gp & 3, go = q * 64 + k;
        g_wih1[((size_t)(dp >> 4) * 256 + gp) * 20 + swz(dp & 15)] =
            (dp < 74) ? tf32r(wih1[go * 74 + dp]) : 0.0f;
    }
    for (size_t ii = t0; ii < 256 * 48; ii += stride) {
        int i = (int)ii;
        int gp = i / 48, dp = i - gp * 48;
        int k = gp >> 2, q = gp & 3, go = q * 64 + k;
        g_wih2[((size_t)(dp >> 4) * 256 + gp) * 20 + swz(dp & 15)] =
            (dp < 35) ? tf32r(wih2[go * 35 + dp]) : 0.0f;
    }
    // whh (unchanged layout)
    for (size_t ii = t0; ii < 1024 * 256; ii += stride) {
        int i = (int)ii;
        int gp = i >> 8, dp = i & 255;
        int k = gp >> 2, q = gp & 3, go = q * 256 + k;
        g_whh0[gp * 256 + swz(dp)] = tf32r(whh0[go * 256 + dp]);
    }
    for (size_t ii = t0; ii < 256 * 64; ii += stride) {
        int i = (int)ii;
        int gp = i >> 6, dp = i & 63;
        int k = gp >> 2, q = gp & 3, go = q * 64 + k;
        g_whh1[gp * 64 + swz(dp)] = tf32r(whh1[go * 64 + dp]);
        g_whh2[gp * 64 + swz(dp)] = tf32r(whh2[go * 64 + dp]);
    }
    for (size_t ii = t0; ii < 1024; ii += stride) {
        int i = (int)ii;
        int k = i >> 2, q = i & 3, go = q * 256 + k;
        g_bias0[i] = bih0[go] + bhh0[go];
    }
    for (size_t ii = t0; ii < 256; ii += stride) {
        int i = (int)ii;
        int k = i >> 2, q = i & 3, go = q * 64 + k;
        g_bias1[i] = bih1[go] + bhh1[go];
        g_bias2[i] = bih2[go] + bhh2[go];
    }
}

// ---------------- launch 1: pad x -> xp [kt][row][20] ----------------
__global__ void prep_x_kernel(
    const float* __restrict__ x0, const float* __restrict__ x1, const float* __restrict__ x2)
{
    size_t stride = (size_t)gridDim.x * blockDim.x;
    size_t t0 = (size_t)blockIdx.x * blockDim.x + threadIdx.x;

    for (size_t i = t0; i < (size_t)65536 * 304; i += stride) {
        int r = (int)(i / 304), d = (int)(i - (size_t)r * 304);
        g_xp0[((size_t)(d >> 4) * 65536 + r) * 20 + swz(d & 15)] =
            (d < 300) ? tf32r(x0[(size_t)r * 300 + d]) : 0.0f;
    }
    for (size_t i = t0; i < (size_t)65536 * 80; i += stride) {
        int r = (int)(i / 80), d = (int)(i - (size_t)r * 80);
        g_xp1[((size_t)(d >> 4) * 65536 + r) * 20 + swz(d & 15)] =
            (d < 74) ? tf32r(x1[(size_t)r * 74 + d]) : 0.0f;
    }
    for (size_t i = t0; i < (size_t)65536 * 48; i += stride) {
        int r = (int)(i / 48), d = (int)(i - (size_t)r * 48);
        g_xp2[((size_t)(d >> 4) * 65536 + r) * 20 + swz(d & 15)] =
            (d < 35) ? tf32r(x2[(size_t)r * 35 + d]) : 0.0f;
    }
}

// ---------------- launch 2: init ----------------
__global__ void init_kernel() {
    int stride = gridDim.x * blockDim.x;
    int i0 = blockIdx.x * blockDim.x + threadIdx.x;
    for (int i = i0; i < 16 * 32; i += stride) g_bar0[i] = 0u;
    for (int i = i0; i < B_SZ * 264; i += stride) g_h0[0][i] = 0.0f;
    for (int i = i0; i < B_SZ * 72; i += stride) { g_h1[0][i] = 0.0f; g_h2[0][i] = 0.0f; }
    for (int i = i0; i < B_SZ * 64; i += stride) { g_c1[i] = 0.0f; g_c2[i] = 0.0f; }
}

// ---------------- launch 3: projections, 128x256 tiles, 3-stage bulk pipeline ------
__device__ __forceinline__ void proj_impl(
    const float* __restrict__ XP, const float* __restrict__ W,
    const float* __restrict__ bias, float* __restrict__ XG,
    int G, int KT, int colBase, int rowBase, float* psm)
{
    int tid = threadIdx.x, lane = tid & 31, warp = tid >> 5;
    int gp = lane >> 2, tg = lane & 3;
    int wm = warp >> 1, wn = warp & 1; // 4m x 2n warps; warp tile 32 x 128

    uint32_t mb = s2u(psm);       // 3 mbarriers (8B each)
    float* buf = psm + 32;        // stage s: x[128x20] then w[256x20]

    if (tid == 0) {
        mbar_init(mb, 1); mbar_init(mb + 8, 1); mbar_init(mb + 16, 1);
        FENCE_ASYNC;
    }
    __syncthreads();

    float acc[2][16][4];
#pragma unroll
    for (int i = 0; i < 2; i++)
#pragma unroll
        for (int j = 0; j < 16; j++)
#pragma unroll
            for (int v = 0; v < 4; v++) acc[i][j][v] = 0.0f;

    auto issue = [&](int kt, int s) {
        if (tid == 0) {
            float* xd = buf + s * 7680;
            float* wd = xd + 2560;
            uint32_t m = mb + 8u * s;
            mbar_arrive_tx(m, 30720);
            bulk_g2s(s2u(xd), XP + ((size_t)kt * 65536 + rowBase) * 20, 10240, m);
            bulk_g2s(s2u(wd), W + ((size_t)kt * G + colBase) * 20, 20480, m);
        }
    };

    issue(0, 0);
    issue(1, 1);

    for (int kt = 0; kt < KT; kt++) {
        int s = kt % 3;
        mbar_wait(mb + 8u * s, (uint32_t)((kt / 3) & 1));
        float* xb = buf + s * 7680;
        float* wb = xb + 2560;
#pragma unroll
        for (int kk = 0; kk < 2; kk++) {
            uint32_t a[2][4];
#pragma unroll
            for (int mt = 0; mt < 2; mt++) {
                int ar = (wm * 32 + mt * 16 + gp) * 20 + kk * 8 + tg * 2;
                float2 lo = *(float2*)&xb[ar];
                float2 hi = *(float2*)&xb[ar + 160];
                a[mt][0] = __float_as_uint(lo.x);
                a[mt][1] = __float_as_uint(hi.x);
                a[mt][2] = __float_as_uint(lo.y);
                a[mt][3] = __float_as_uint(hi.y);
            }
#pragma unroll
            for (int nt = 0; nt < 16; nt++) {
                int br = (wn * 128 + nt * 8 + gp) * 20 + kk * 8 + tg * 2;
                float2 bv = *(float2*)&wb[br];
                uint32_t b[2] = {__float_as_uint(bv.x), __float_as_uint(bv.y)};
#pragma unroll
                for (int mt = 0; mt < 2; mt++) mma_tf32(acc[mt][nt], a[mt], b);
            }
        }
        __syncthreads();                 // all threads done with stage (kt-1)%3 region
        if (kt + 2 < KT) issue(kt + 2, (kt + 2) % 3);
    }

#pragma unroll
    for (int mt = 0; mt < 2; mt++)
#pragma unroll
        for (int nt = 0; nt < 16; nt++) {
            int r0 = rowBase + wm * 32 + mt * 16 + gp;
            int col = colBase + wn * 128 + nt * 8 + 2 * tg;
            float bx = bias[col], by = bias[col + 1];
            int tt0 = r0 & 127, bb0 = r0 >> 7;
            int r1 = r0 + 8;
            int tt1 = r1 & 127, bb1 = r1 >> 7;
            size_t o0, o1;
            if (G == 1024) {
                int bnn = col >> 7, cl = col & 127;
                o0 = (((size_t)tt0 * 8 + bnn) * B_SZ + bb0) * 128 + cl;
                o1 = (((size_t)tt1 * 8 + bnn) * B_SZ + bb1) * 128 + cl;
            } else {
                o0 = ((size_t)tt0 * B_SZ + bb0) * 256 + col;
                o1 = ((size_t)tt1 * B_SZ + bb1) * 256 + col;
            }
            *(float2*)&XG[o0] = make_float2(acc[mt][nt][0] + bx, acc[mt][nt][1] + by);
            *(float2*)&XG[o1] = make_float2(acc[mt][nt][2] + bx, acc[mt][nt][3] + by);
        }
}

__global__ __launch_bounds__(256) void proj_all_kernel() {
    extern __shared__ __align__(16) float psm[];
    int bx = blockIdx.x;
    int rowBase = blockIdx.y * 128;
    if (bx < 4) {
        proj_impl(g_xp0, g_wih0, g_bias0, g_xg0, 1024, 19, bx * 256, rowBase, psm);
    } else if (bx == 4) {
        proj_impl(g_xp1, g_wih1, g_bias1, g_xg1, 256, 5, 0, rowBase, psm);
    } else {
        proj_impl(g_xp2, g_wih2, g_bias2, g_xg2, 256, 3, 0, rowBase, psm);
    }
}

// ---------------- launch 4: persistent recurrence ----------------
__global__ __launch_bounds__(256, 1) void persist_kernel() {
    extern __shared__ __align__(16) float sm[];
    int bid = blockIdx.x, tid = threadIdx.x;
    int lane = tid & 31, warp = tid >> 5;
    int gp = lane >> 2, tg = lane & 3;

    if (bid < 128) {
        // ================= module 0: H=256, G=1024 =================
        int bm = bid >> 3, bn = bid & 7;
        int rowBase = bm * 32, colBase = bn * 128;
        float* hs   = sm + 32;         // 32 x 264
        float* xbuf = hs + 8448;       // 32 x 128
        float* gsm  = xbuf + 4096;     // 32 x 128
        uint32_t mb_h = s2u(sm);
        uint32_t mb_x = mb_h + 8;

        if (tid == 0) { mbar_init(mb_h, 1); mbar_init(mb_x, 1); FENCE_ASYNC; }
        __syncthreads();

        // weights in registers: warp wn owns cols [wn*16, wn*16+16), all K
        int wn = warp;
        uint32_t breg[32][2][2];
#pragma unroll
        for (int kk = 0; kk < 32; kk++)
#pragma unroll
            for (int nt = 0; nt < 2; nt++) {
                float2 v = *(const float2*)
                    &g_whh0[(size_t)(colBase + wn * 16 + nt * 8 + gp) * 256 + kk * 8 + tg * 2];
                breg[kk][nt][0] = __float_as_uint(v.x);
                breg[kk][nt][1] = __float_as_uint(v.y);
            }

        float creg[4] = {0.0f, 0.0f, 0.0f, 0.0f};
        unsigned* cnt = &g_bar0[bm * 32];

        for (int t = 0; t < T_SZ; t++) {
            const float* hin = g_h0[t & 1];
            float* hout = g_h0[(t & 1) ^ 1];

            if (tid == 0) {
                mbar_arrive_tx(mb_h, 33792);
                bulk_g2s(s2u(hs), hin + rowBase * 264, 33792, mb_h);
                mbar_arrive_tx(mb_x, 16384);
                bulk_g2s(s2u(xbuf),
                         g_xg0 + (((size_t)t * 8 + bn) * B_SZ + rowBase) * 128,
                         16384, mb_x);
            }
            mbar_wait(mb_h, (uint32_t)(t & 1));

            float acc[2][2][4];
#pragma unroll
            for (int i = 0; i < 2; i++)
#pragma unroll
                for (int j = 0; j < 2; j++)
#pragma unroll
                    for (int v = 0; v < 4; v++) acc[i][j][v] = 0.0f;

#pragma unroll
            for (int kk = 0; kk < 32; kk++) {
                int kb = kk * 8 + tg * 2;
                float2 lo0 = *(float2*)&hs[gp * 264 + kb];
                float2 hi0 = *(float2*)&hs[(gp + 8) * 264 + kb];
                float2 lo1 = *(float2*)&hs[(gp + 16) * 264 + kb];
                float2 hi1 = *(float2*)&hs[(gp + 24) * 264 + kb];
                uint32_t a0[4] = {__float_as_uint(lo0.x), __float_as_uint(hi0.x),
                                  __float_as_uint(lo0.y), __float_as_uint(hi0.y)};
                uint32_t a1[4] = {__float_as_uint(lo1.x), __float_as_uint(hi1.x),
                                  __float_as_uint(lo1.y), __float_as_uint(hi1.y)};
                mma_tf32(acc[0][0], a0, breg[kk][0]);
                mma_tf32(acc[0][1], a0, breg[kk][1]);
                mma_tf32(acc[1][0], a1, breg[kk][0]);
                mma_tf32(acc[1][1], a1, breg[kk][1]);
            }

#pragma unroll
            for (int mt = 0; mt < 2; mt++)
#pragma unroll
                for (int nt = 0; nt < 2; nt++) {
                    int r = mt * 16 + gp, col = wn * 16 + nt * 8 + tg * 2;
                    *(float2*)&gsm[r * 128 + col] =
                        make_float2(acc[mt][nt][0], acc[mt][nt][1]);
                    *(float2*)&gsm[(r + 8) * 128 + col] =
                        make_float2(acc[mt][nt][2], acc[mt][nt][3]);
                }
            __syncthreads();
            mbar_wait(mb_x, (uint32_t)(t & 1));

#pragma unroll
            for (int j = 0; j < 4; j++) {
                int idx = tid + j * 256;
                int bl = idx >> 5, kl = idx & 31;
                float4 gt = *(float4*)&gsm[bl * 128 + 4 * kl];
                float4 xv = *(float4*)&xbuf[bl * 128 + 4 * kl];
                float ii = sigm(gt.x + xv.x);
                float ff = sigm(gt.y + xv.y);
                float gg = tanhfast(gt.z + xv.z);
                float oo = sigm(gt.w + xv.w);
                float cn = ff * creg[j] + ii * gg;
                creg[j] = cn;
                float hn = oo * tanhfast(cn);
                hout[(rowBase + bl) * 264 + swz(bn * 32 + kl)] = tf32r(hn);
            }

            if (t + 1 < T_SZ) {
                __syncthreads();
                if (tid == 0) {
                    __threadfence();
                    atomicAdd(cnt, 1u);
                    unsigned tgt = 8u * (unsigned)(t + 1);
                    while (*(volatile unsigned*)cnt < tgt) {}
                    __threadfence();
                }
                __syncthreads();
            }
        }
    } else {
        // ================= modules 1,2: H=64, G=256, fully independent ============
        int sub = bid - 128;
        int mod = sub >> 3, bm = sub & 7;
        int rowBase = bm * 64;
        const float* whh = mod ? g_whh2 : g_whh1;
        const float* xgb = mod ? g_xg2 : g_xg1;
        float* cb = mod ? g_c2 : g_c1;

        float* ws   = sm + 32;         // 256 x 72
        float* hs   = ws + 18432;      // 64 x 72
        float* gsm  = hs + 4608;       // 64 x 256
        float* xbuf = gsm + 16384;     // 64 x 256
        uint32_t mb_h = s2u(sm);
        uint32_t mb_x = mb_h + 8;

        if (tid == 0) { mbar_init(mb_h, 1); mbar_init(mb_x, 1); FENCE_ASYNC; }
        __syncthreads();

        for (int idx = tid; idx < 256 * 16; idx += 256) {
            int r = idx >> 4, c = idx & 15;
            *(float4*)&ws[r * 72 + c * 4] = *(const float4*)&whh[r * 64 + c * 4];
        }
        __syncthreads();

        int wm = warp >> 2, wn = warp & 3;

        for (int t = 0; t < T_SZ; t++) {
            const float* hin = mod ? g_h2[t & 1] : g_h1[t & 1];
            float* hout = mod ? g_h2[(t & 1) ^ 1] : g_h1[(t & 1) ^ 1];

            if (tid == 0) {
                mbar_arrive_tx(mb_h, 18432);
                bulk_g2s(s2u(hs), hin + rowBase * 72, 18432, mb_h);
                mbar_arrive_tx(mb_x, 65536);
                bulk_g2s(s2u(xbuf),
                         xgb + ((size_t)t * B_SZ + rowBase) * 256, 65536, mb_x);
            }
            mbar_wait(mb_h, (uint32_t)(t & 1));

            float acc[2][8][4];
#pragma unroll
            for (int i = 0; i < 2; i++)
#pragma unroll
                for (int j = 0; j < 8; j++)
#pragma unroll
                    for (int v = 0; v < 4; v++) acc[i][j][v] = 0.0f;

#pragma unroll
            for (int kk = 0; kk < 8; kk++) {
                uint32_t a[2][4];
#pragma unroll
                for (int mt = 0; mt < 2; mt++) {
                    int ar = (wm * 32 + mt * 16 + gp) * 72 + kk * 8 + tg * 2;
                    float2 lo = *(float2*)&hs[ar];
                    float2 hi = *(float2*)&hs[ar + 576];
                    a[mt][0] = __float_as_uint(lo.x);
                    a[mt][1] = __float_as_uint(hi.x);
                    a[mt][2] = __float_as_uint(lo.y);
                    a[mt][3] = __float_as_uint(hi.y);
                }
#pragma unroll
                for (int nt = 0; nt < 8; nt++) {
                    int br = (wn * 64 + nt * 8 + gp) * 72 + kk * 8 + tg * 2;
                    float2 bv = *(float2*)&ws[br];
                    uint32_t b[2] = {__float_as_uint(bv.x), __float_as_uint(bv.y)};
#pragma unroll
                    for (int mt = 0; mt < 2; mt++) mma_tf32(acc[mt][nt], a[mt], b);
                }
            }

#pragma unroll
            for (int mt = 0; mt < 2; mt++)
#pragma unroll
                for (int nt = 0; nt < 8; nt++) {
                    int r = wm * 32 + mt * 16 + gp;
                    int col = wn * 64 + nt * 8 + 2 * tg;
                    *(float2*)&gsm[r * 256 + col] = make_float2(acc[mt][nt][0], acc[mt][nt][1]);
                    *(float2*)&gsm[(r + 8) * 256 + col] = make_float2(acc[mt][nt][2], acc[mt][nt][3]);
                }
            __syncthreads();
            mbar_wait(mb_x, (uint32_t)(t & 1));

            for (int idx = tid; idx < 4096; idx += 256) {
                int kl = idx & 63, bl = idx >> 6;
                float4 gt = *(float4*)&gsm[bl * 256 + 4 * kl];
                int bg = rowBase + bl;
                float4 xv = *(float4*)&xbuf[bl * 256 + 4 * kl];
                float ii = sigm(gt.x + xv.x);
                float ff = sigm(gt.y + xv.y);
                float gg = tanhfast(gt.z + xv.z);
                float oo = sigm(gt.w + xv.w);
                float cold = cb[bg * 64 + kl];
                float cn = ff * cold + ii * gg;
                float hn = oo * tanhfast(cn);
                cb[bg * 64 + kl] = cn;
                hout[bg * 72 + swz(kl)] = tf32r(hn);
            }
            __syncthreads();
        }
    }
}

// ---------------- launch 5: head ----------------
__global__ void head_kernel(const float* __restrict__ w1, const float* __restrict__ b1,
                            const float* __restrict__ w2, const float* __restrict__ b2,
                            float* __restrict__ out) {
    __shared__ float hc[8 * 384];
    __shared__ float red[256];
    int tid = threadIdx.x;
    int rowBase = blockIdx.x * 8;

    for (int i = tid; i < 8 * 384; i += 256) {
        int r = i / 384, d = i - r * 384;
        int bg = rowBase + r;
        float v;
        if (d < 256)      v = g_h0[0][bg * 264 + swz(d)];
        else if (d < 320) v = g_h1[0][bg * 72 + swz(d - 256)];
        else              v = g_h2[0][bg * 72 + swz(d - 320)];
        hc[i] = v;
    }
    __syncthreads();

    for (int pass = 0; pass < 2; pass++) {
        int row = pass * 4 + (tid >> 6);
        int cell = tid & 63;
        const float* wr = w1 + cell * 384;
        const float* hr = hc + row * 384;
        float a = b1[cell];
#pragma unroll 4
        for (int d = 0; d < 384; d++) a += hr[d] * wr[d];
        a = fmaxf(a, 0.0f);
        red[tid] = a * w2[cell];
        __syncthreads();
        if (cell == 0) {
            float s = 0.0f;
#pragma unroll
            for (int j = 0; j < 64; j++) s += red[tid + j];
            out[rowBase + row] = s + b2[0];
        }
        __syncthreads();
    }
}

// ---------------- launch ----------------
extern "C" void kernel_launch(void* const* d_in, const int* in_sizes, int n_in,
                              void* d_out, int out_size) {
    const float* x0    = (const float*)d_in[0];
    const float* x1    = (const float*)d_in[1];
    const float* x2    = (const float*)d_in[2];
    const float* w_ih0 = (const float*)d_in[3];
    const float* w_hh0 = (const float*)d_in[4];
    const float* b_ih0 = (const float*)d_in[5];
    const float* b_hh0 = (const float*)d_in[6];
    const float* w_ih1 = (const float*)d_in[7];
    const float* w_hh1 = (const float*)d_in[8];
    const float* b_ih1 = (const float*)d_in[9];
    const float* b_hh1 = (const float*)d_in[10];
    const float* w_ih2 = (const float*)d_in[11];
    const float* w_hh2 = (const float*)d_in[12];
    const float* b_ih2 = (const float*)d_in[13];
    const float* b_hh2 = (const float*)d_in[14];
    const float* w1    = (const float*)d_in[15];
    const float* b1    = (const float*)d_in[16];
    const float* w2    = (const float*)d_in[17];
    const float* b2    = (const float*)d_in[18];
    float* out = (float*)d_out;

    cudaFuncSetAttribute(persist_kernel, cudaFuncAttributeMaxDynamicSharedMemorySize,
                         SMEM_PERSIST);
    cudaFuncSetAttribute(proj_all_kernel, cudaFuncAttributeMaxDynamicSharedMemorySize,
                         SMEM_PROJ);

    // launch 0
    prep_w_kernel<<<512, 256>>>(w_ih0, w_hh0, b_ih0, b_hh0,
                                w_ih1, w_hh1, b_ih1, b_hh1,
                                w_ih2, w_hh2, b_ih2, b_hh2);
    // launch 1
    prep_x_kernel<<<1024, 256>>>(x0, x1, x2);
    // launch 2
    init_kernel<<<256, 256>>>();
    // launch 3  (ncu capture index) — the projection GEMM
    proj_all_kernel<<<dim3(6, 512), 256, SMEM_PROJ>>>();
    // launch 4
    persist_kernel<<<NBLK, 256, SMEM_PERSIST>>>();
    // launch 5
    head_kernel<<<64, 256>>>(w1, b1, w2, b2, out);
}

// round 10
// speedup vs baseline: 1.1681x; 1.0343x over previous
#include <cuda_runtime.h>
#include <cstdint>

#define B_SZ 512
#define T_SZ 128
#define NBLK 144
#define SMEM_PERSIST 223360
#define SMEM_PROJ    61504

// ---------------- __device__ scratch (no allocations allowed) ----------------
// xg0: [t][bn(8)][b(512)][128]
__device__ __align__(128) float g_xg0[(size_t)T_SZ * 8 * B_SZ * 128];
__device__ __align__(128) float g_xg1[(size_t)T_SZ * B_SZ * 256];
__device__ __align__(128) float g_xg2[(size_t)T_SZ * B_SZ * 256];
// xp: [kt][row(65536)][20]  (16 swizzled k-values + 4 pad)
__device__ __align__(128) float g_xp0[(size_t)19 * 65536 * 20];
__device__ __align__(128) float g_xp1[(size_t)5 * 65536 * 20];
__device__ __align__(128) float g_xp2[(size_t)3 * 65536 * 20];
// wih: [kt][gate][20]
__device__ __align__(128) float g_wih0[19 * 1024 * 20];
__device__ __align__(128) float g_wih1[5 * 256 * 20];
__device__ __align__(128) float g_wih2[3 * 256 * 20];
__device__ __align__(128) float g_whh0[1024 * 256];   // [gate][256], K pair-swizzled
__device__ __align__(128) float g_whh1[256 * 64];
__device__ __align__(128) float g_whh2[256 * 64];
__device__ __align__(128) float g_bias0[1024];
__device__ __align__(128) float g_bias1[256];
__device__ __align__(128) float g_bias2[256];
// h: row-padded so a tile is ONE contiguous bulk copy landing bank-conflict-free
__device__ __align__(128) float g_h0[2][B_SZ * 264];  // stride 264, tf32, pair-swizzled
__device__ __align__(128) float g_h1[2][B_SZ * 72];   // stride 72
__device__ __align__(128) float g_h2[2][B_SZ * 72];
__device__ __align__(128) float g_c1[B_SZ * 64];
__device__ __align__(128) float g_c2[B_SZ * 64];
__device__ __align__(128) unsigned g_bar0[16 * 32];

// ---------------- helpers ----------------
__device__ __forceinline__ int swz(int k) {
    return (k & ~7) | ((k & 3) << 1) | ((k >> 2) & 1);
}

__device__ __forceinline__ float tf32r(float x) {
    uint32_t u;
    asm("cvt.rna.tf32.f32 %0, %1;" : "=r"(u) : "f"(x));
    return __uint_as_float(u);
}

__device__ __forceinline__ void mma_tf32(float c[4], const uint32_t a[4], const uint32_t b[2]) {
    asm volatile(
        "mma.sync.aligned.m16n8k8.row.col.f32.tf32.tf32.f32 "
        "{%0,%1,%2,%3}, {%4,%5,%6,%7}, {%8,%9}, {%0,%1,%2,%3};"
        : "+f"(c[0]), "+f"(c[1]), "+f"(c[2]), "+f"(c[3])
        : "r"(a[0]), "r"(a[1]), "r"(a[2]), "r"(a[3]), "r"(b[0]), "r"(b[1]));
}

__device__ __forceinline__ float fex2(float x) {
    float r; asm("ex2.approx.f32 %0, %1;" : "=f"(r) : "f"(x)); return r;
}
__device__ __forceinline__ float frcp(float x) {
    float r; asm("rcp.approx.f32 %0, %1;" : "=f"(r) : "f"(x)); return r;
}
__device__ __forceinline__ float sigm(float x) {
    return frcp(1.0f + fex2(-1.4426950408889634f * x));
}
__device__ __forceinline__ float tanhfast(float x) {
    return 2.0f * frcp(1.0f + fex2(-2.8853900817779268f * x)) - 1.0f;
}

// ---- bulk-copy + mbarrier primitives ----
__device__ __forceinline__ uint32_t s2u(const void* p) {
    return (uint32_t)__cvta_generic_to_shared(p);
}
__device__ __forceinline__ void mbar_init(uint32_t mb, uint32_t cnt) {
    asm volatile("mbarrier.init.shared.b64 [%0], %1;" :: "r"(mb), "r"(cnt) : "memory");
}
__device__ __forceinline__ void mbar_arrive_tx(uint32_t mb, uint32_t bytes) {
    asm volatile("mbarrier.arrive.expect_tx.shared.b64 _, [%0], %1;"
                 :: "r"(mb), "r"(bytes) : "memory");
}
__device__ __forceinline__ void mbar_wait(uint32_t mb, uint32_t parity) {
    asm volatile(
        "{\n\t.reg .pred P;\n"
        "W%=:\n\t"
        "mbarrier.try_wait.parity.shared.b64 P, [%0], %1;\n\t"
        "@!P bra W%=;\n\t}"
        :: "r"(mb), "r"(parity) : "memory");
}
__device__ __forceinline__ void bulk_g2s(uint32_t dst, const void* src,
                                         uint32_t bytes, uint32_t mb) {
    asm volatile(
        "cp.async.bulk.shared::cluster.global.mbarrier::complete_tx::bytes "
        "[%0], [%1], %2, [%3];"
        :: "r"(dst), "l"(src), "r"(bytes), "r"(mb) : "memory");
}
#define FENCE_ASYNC asm volatile("fence.proxy.async.shared::cta;" ::: "memory")

// ---------------- launch 0: prep weights ----------------
__global__ void prep_w_kernel(
    const float* __restrict__ wih0, const float* __restrict__ whh0,
    const float* __restrict__ bih0, const float* __restrict__ bhh0,
    const float* __restrict__ wih1, const float* __restrict__ whh1,
    const float* __restrict__ bih1, const float* __restrict__ bhh1,
    const float* __restrict__ wih2, const float* __restrict__ whh2,
    const float* __restrict__ bih2, const float* __restrict__ bhh2)
{
    size_t stride = (size_t)gridDim.x * blockDim.x;
    size_t t0 = (size_t)blockIdx.x * blockDim.x + threadIdx.x;

    // wih -> [kt][gate'][20], gate-interleaved rows g' = 4k+q, within-16 swizzle
    for (size_t ii = t0; ii < 1024 * 304; ii += stride) {
        int i = (int)ii;
        int gp = i / 304, dp = i - gp * 304;
        int k = gp >> 2, q = gp & 3, go = q * 256 + k;
        g_wih0[((size_t)(dp >> 4) * 1024 + gp) * 20 + swz(dp & 15)] =
            (dp < 300) ? tf32r(wih0[go * 300 + dp]) : 0.0f;
    }
    for (size_t ii = t0; ii < 256 * 80; ii += stride) {
        int i = (int)ii;
        int gp = i / 80, dp = i - gp * 80;
        int k = gp >> 2, q = gp & 3, go = q * 64 + k;
        g_wih1[((size_t)(dp >> 4) * 256 + gp) * 20 + swz(dp & 15)] =
            (dp < 74) ? tf32r(wih1[go * 74 + dp]) : 0.0f;
    }
    for (size_t ii = t0; ii < 256 * 48; ii += stride) {
        int i = (int)ii;
        int gp = i / 48, dp = i - gp * 48;
        int k = gp >> 2, q = gp & 3, go = q * 64 + k;
        g_wih2[((size_t)(dp >> 4) * 256 + gp) * 20 + swz(dp & 15)] =
            (dp < 35) ? tf32r(wih2[go * 35 + dp]) : 0.0f;
    }
    for (size_t ii = t0; ii < 1024 * 256; ii += stride) {
        int i = (int)ii;
        int gp = i >> 8, dp = i & 255;
        int k = gp >> 2, q = gp & 3, go = q * 256 + k;
        g_whh0[gp * 256 + swz(dp)] = tf32r(whh0[go * 256 + dp]);
    }
    for (size_t ii = t0; ii < 256 * 64; ii += stride) {
        int i = (int)ii;
        int gp = i >> 6, dp = i & 63;
        int k = gp >> 2, q = gp & 3, go = q * 64 + k;
        g_whh1[gp * 64 + swz(dp)] = tf32r(whh1[go * 64 + dp]);
        g_whh2[gp * 64 + swz(dp)] = tf32r(whh2[go * 64 + dp]);
    }
    for (size_t ii = t0; ii < 1024; ii += stride) {
        int i = (int)ii;
        int k = i >> 2, q = i & 3, go = q * 256 + k;
        g_bias0[i] = bih0[go] + bhh0[go];
    }
    for (size_t ii = t0; ii < 256; ii += stride) {
        int i = (int)ii;
        int k = i >> 2, q = i & 3, go = q * 64 + k;
        g_bias1[i] = bih1[go] + bhh1[go];
        g_bias2[i] = bih2[go] + bhh2[go];
    }
}

// ---------------- launch 1: pad x -> xp [kt][row][20], coalesced 80B writes ---------
__device__ __forceinline__ void prep_x_one(
    const float* __restrict__ X, float* __restrict__ XP,
    int D, int KT, size_t task0, size_t stride)
{
    size_t ntask = (size_t)KT * 65536;
    for (size_t i = task0; i < ntask; i += stride) {
        int kt = (int)(i >> 16);
        int r = (int)(i & 65535);
        int k0 = kt * 16;
        float o[20];
#pragma unroll
        for (int c = 0; c < 16; c++) {
            int d = k0 + c;
            o[swz(c)] = (d < D) ? tf32r(X[(size_t)r * D + d]) : 0.0f;
        }
        o[16] = o[17] = o[18] = o[19] = 0.0f;
        float4* dst = (float4*)&XP[i * 20];
#pragma unroll
        for (int v = 0; v < 5; v++) dst[v] = *(float4*)&o[v * 4];
    }
}

__global__ void prep_x_kernel(
    const float* __restrict__ x0, const float* __restrict__ x1, const float* __restrict__ x2)
{
    size_t stride = (size_t)gridDim.x * blockDim.x;
    size_t t0 = (size_t)blockIdx.x * blockDim.x + threadIdx.x;
    prep_x_one(x0, g_xp0, 300, 19, t0, stride);
    prep_x_one(x1, g_xp1, 74, 5, t0, stride);
    prep_x_one(x2, g_xp2, 35, 3, t0, stride);
}

// ---------------- launch 2: init ----------------
__global__ void init_kernel() {
    int stride = gridDim.x * blockDim.x;
    int i0 = blockIdx.x * blockDim.x + threadIdx.x;
    for (int i = i0; i < 16 * 32; i += stride) g_bar0[i] = 0u;
    for (int i = i0; i < B_SZ * 264; i += stride) g_h0[0][i] = 0.0f;
    for (int i = i0; i < B_SZ * 72; i += stride) { g_h1[0][i] = 0.0f; g_h2[0][i] = 0.0f; }
    for (int i = i0; i < B_SZ * 64; i += stride) { g_c1[i] = 0.0f; g_c2[i] = 0.0f; }
}

// ---------------- launch 3: projections, 128x128 tiles, 3-stage bulk, 2 CTA/SM -----
__device__ __forceinline__ void proj_impl(
    const float* __restrict__ XP, const float* __restrict__ W,
    const float* __restrict__ bias, float* __restrict__ XG,
    int G, int KT, int colBase, int rowBase, float* psm)
{
    int tid = threadIdx.x, lane = tid & 31, warp = tid >> 5;
    int gp = lane >> 2, tg = lane & 3;
    int wm = warp >> 1, wn = warp & 1; // 4m x 2n warps; warp tile 32 x 64

    uint32_t mb = s2u(psm);       // 3 mbarriers
    float* buf = psm + 32;        // stage s: x[128x20] then w[128x20]

    if (tid == 0) {
        mbar_init(mb, 1); mbar_init(mb + 8, 1); mbar_init(mb + 16, 1);
        FENCE_ASYNC;
    }
    __syncthreads();

    float acc[2][8][4];
#pragma unroll
    for (int i = 0; i < 2; i++)
#pragma unroll
        for (int j = 0; j < 8; j++)
#pragma unroll
            for (int v = 0; v < 4; v++) acc[i][j][v] = 0.0f;

    auto issue = [&](int kt, int s) {
        if (tid == 0) {
            float* xd = buf + s * 5120;
            float* wd = xd + 2560;
            uint32_t m = mb + 8u * s;
            mbar_arrive_tx(m, 20480);
            bulk_g2s(s2u(xd), XP + ((size_t)kt * 65536 + rowBase) * 20, 10240, m);
            bulk_g2s(s2u(wd), W + ((size_t)kt * G + colBase) * 20, 10240, m);
        }
    };

    issue(0, 0);
    issue(1, 1);

    for (int kt = 0; kt < KT; kt++) {
        int s = kt % 3;
        mbar_wait(mb + 8u * s, (uint32_t)((kt / 3) & 1));
        float* xb = buf + s * 5120;
        float* wb = xb + 2560;
#pragma unroll
        for (int kk = 0; kk < 2; kk++) {
            uint32_t a[2][4];
#pragma unroll
            for (int mt = 0; mt < 2; mt++) {
                int ar = (wm * 32 + mt * 16 + gp) * 20 + kk * 8 + tg * 2;
                float2 lo = *(float2*)&xb[ar];
                float2 hi = *(float2*)&xb[ar + 160];
                a[mt][0] = __float_as_uint(lo.x);
                a[mt][1] = __float_as_uint(hi.x);
                a[mt][2] = __float_as_uint(lo.y);
                a[mt][3] = __float_as_uint(hi.y);
            }
#pragma unroll
            for (int nt = 0; nt < 8; nt++) {
                int br = (wn * 64 + nt * 8 + gp) * 20 + kk * 8 + tg * 2;
                float2 bv = *(float2*)&wb[br];
                uint32_t b[2] = {__float_as_uint(bv.x), __float_as_uint(bv.y)};
#pragma unroll
                for (int mt = 0; mt < 2; mt++) mma_tf32(acc[mt][nt], a[mt], b);
            }
        }
        __syncthreads();
        if (kt + 2 < KT) issue(kt + 2, (kt + 2) % 3);
    }

#pragma unroll
    for (int mt = 0; mt < 2; mt++)
#pragma unroll
        for (int nt = 0; nt < 8; nt++) {
            int r0 = rowBase + wm * 32 + mt * 16 + gp;
            int col = colBase + wn * 64 + nt * 8 + 2 * tg;
            float bx = bias[col], by = bias[col + 1];
            int tt0 = r0 & 127, bb0 = r0 >> 7;
            int r1 = r0 + 8;
            int tt1 = r1 & 127, bb1 = r1 >> 7;
            size_t o0, o1;
            if (G == 1024) {
                int bnn = col >> 7, cl = col & 127;
                o0 = (((size_t)tt0 * 8 + bnn) * B_SZ + bb0) * 128 + cl;
                o1 = (((size_t)tt1 * 8 + bnn) * B_SZ + bb1) * 128 + cl;
            } else {
                o0 = ((size_t)tt0 * B_SZ + bb0) * 256 + col;
                o1 = ((size_t)tt1 * B_SZ + bb1) * 256 + col;
            }
            *(float2*)&XG[o0] = make_float2(acc[mt][nt][0] + bx, acc[mt][nt][1] + by);
            *(float2*)&XG[o1] = make_float2(acc[mt][nt][2] + bx, acc[mt][nt][3] + by);
        }
}

__global__ __launch_bounds__(256, 2) void proj_all_kernel() {
    extern __shared__ __align__(16) float psm[];
    int bx = blockIdx.x;
    int rowBase = blockIdx.y * 128;
    if (bx < 8) {
        proj_impl(g_xp0, g_wih0, g_bias0, g_xg0, 1024, 19, bx * 128, rowBase, psm);
    } else if (bx < 10) {
        proj_impl(g_xp1, g_wih1, g_bias1, g_xg1, 256, 5, (bx - 8) * 128, rowBase, psm);
    } else {
        proj_impl(g_xp2, g_wih2, g_bias2, g_xg2, 256, 3, (bx - 10) * 128, rowBase, psm);
    }
}

// ---------------- launch 4: persistent recurrence ----------------
__global__ __launch_bounds__(256, 1) void persist_kernel() {
    extern __shared__ __align__(16) float sm[];
    int bid = blockIdx.x, tid = threadIdx.x;
    int lane = tid & 31, warp = tid >> 5;
    int gp = lane >> 2, tg = lane & 3;

    if (bid < 128) {
        // ================= module 0: H=256, G=1024 =================
        int bm = bid >> 3, bn = bid & 7;
        int rowBase = bm * 32, colBase = bn * 128;
        float* hs   = sm + 32;         // 32 x 264
        float* xbuf = hs + 8448;       // 32 x 128
        float* gsm  = xbuf + 4096;     // 32 x 128
        uint32_t mb_h = s2u(sm);
        uint32_t mb_x = mb_h + 8;

        if (tid == 0) { mbar_init(mb_h, 1); mbar_init(mb_x, 1); FENCE_ASYNC; }
        __syncthreads();

        int wn = warp;
        uint32_t breg[32][2][2];
#pragma unroll
        for (int kk = 0; kk < 32; kk++)
#pragma unroll
            for (int nt = 0; nt < 2; nt++) {
                float2 v = *(const float2*)
                    &g_whh0[(size_t)(colBase + wn * 16 + nt * 8 + gp) * 256 + kk * 8 + tg * 2];
                breg[kk][nt][0] = __float_as_uint(v.x);
                breg[kk][nt][1] = __float_as_uint(v.y);
            }

        float creg[4] = {0.0f, 0.0f, 0.0f, 0.0f};
        unsigned* cnt = &g_bar0[bm * 32];

        for (int t = 0; t < T_SZ; t++) {
            const float* hin = g_h0[t & 1];
            float* hout = g_h0[(t & 1) ^ 1];

            if (tid == 0) {
                mbar_arrive_tx(mb_h, 33792);
                bulk_g2s(s2u(hs), hin + rowBase * 264, 33792, mb_h);
                mbar_arrive_tx(mb_x, 16384);
                bulk_g2s(s2u(xbuf),
                         g_xg0 + (((size_t)t * 8 + bn) * B_SZ + rowBase) * 128,
                         16384, mb_x);
            }
            mbar_wait(mb_h, (uint32_t)(t & 1));

            float acc[2][2][4];
#pragma unroll
            for (int i = 0; i < 2; i++)
#pragma unroll
                for (int j = 0; j < 2; j++)
#pragma unroll
                    for (int v = 0; v < 4; v++) acc[i][j][v] = 0.0f;

#pragma unroll
            for (int kk = 0; kk < 32; kk++) {
                int kb = kk * 8 + tg * 2;
                float2 lo0 = *(float2*)&hs[gp * 264 + kb];
                float2 hi0 = *(float2*)&hs[(gp + 8) * 264 + kb];
                float2 lo1 = *(float2*)&hs[(gp + 16) * 264 + kb];
                float2 hi1 = *(float2*)&hs[(gp + 24) * 264 + kb];
                uint32_t a0[4] = {__float_as_uint(lo0.x), __float_as_uint(hi0.x),
                                  __float_as_uint(lo0.y), __float_as_uint(hi0.y)};
                uint32_t a1[4] = {__float_as_uint(lo1.x), __float_as_uint(hi1.x),
                                  __float_as_uint(lo1.y), __float_as_uint(hi1.y)};
                mma_tf32(acc[0][0], a0, breg[kk][0]);
                mma_tf32(acc[0][1], a0, breg[kk][1]);
                mma_tf32(acc[1][0], a1, breg[kk][0]);
                mma_tf32(acc[1][1], a1, breg[kk][1]);
            }

#pragma unroll
            for (int mt = 0; mt < 2; mt++)
#pragma unroll
                for (int nt = 0; nt < 2; nt++) {
                    int r = mt * 16 + gp, col = wn * 16 + nt * 8 + tg * 2;
                    *(float2*)&gsm[r * 128 + col] =
                        make_float2(acc[mt][nt][0], acc[mt][nt][1]);
                    *(float2*)&gsm[(r + 8) * 128 + col] =
                        make_float2(acc[mt][nt][2], acc[mt][nt][3]);
                }
            __syncthreads();
            mbar_wait(mb_x, (uint32_t)(t & 1));

#pragma unroll
            for (int j = 0; j < 4; j++) {
                int idx = tid + j * 256;
                int bl = idx >> 5, kl = idx & 31;
                float4 gt = *(float4*)&gsm[bl * 128 + 4 * kl];
                float4 xv = *(float4*)&xbuf[bl * 128 + 4 * kl];
                float ii = sigm(gt.x + xv.x);
                float ff = sigm(gt.y + xv.y);
                float gg = tanhfast(gt.z + xv.z);
                float oo = sigm(gt.w + xv.w);
                float cn = ff * creg[j] + ii * gg;
                creg[j] = cn;
                float hn = oo * tanhfast(cn);
                hout[(rowBase + bl) * 264 + swz(bn * 32 + kl)] = tf32r(hn);
            }

            if (t + 1 < T_SZ) {
                __syncthreads();
                if (tid == 0) {
                    __threadfence();
                    atomicAdd(cnt, 1u);
                    unsigned tgt = 8u * (unsigned)(t + 1);
                    while (*(volatile unsigned*)cnt < tgt) {}
                    __threadfence();
                }
                __syncthreads();
            }
        }
    } else {
        // ================= modules 1,2: H=64, G=256, fully independent ============
        int sub = bid - 128;
        int mod = sub >> 3, bm = sub & 7;
        int rowBase = bm * 64;
        const float* whh = mod ? g_whh2 : g_whh1;
        const float* xgb = mod ? g_xg2 : g_xg1;
        float* cb = mod ? g_c2 : g_c1;

        float* ws   = sm + 32;         // 256 x 72
        float* hs   = ws + 18432;      // 64 x 72
        float* gsm  = hs + 4608;       // 64 x 256
        float* xbuf = gsm + 16384;     // 64 x 256
        uint32_t mb_h = s2u(sm);
        uint32_t mb_x = mb_h + 8;

        if (tid == 0) { mbar_init(mb_h, 1); mbar_init(mb_x, 1); FENCE_ASYNC; }
        __syncthreads();

        for (int idx = tid; idx < 256 * 16; idx += 256) {
            int r = idx >> 4, c = idx & 15;
            *(float4*)&ws[r * 72 + c * 4] = *(const float4*)&whh[r * 64 + c * 4];
        }
        __syncthreads();

        int wm = warp >> 2, wn = warp & 3;

        for (int t = 0; t < T_SZ; t++) {
            const float* hin = mod ? g_h2[t & 1] : g_h1[t & 1];
            float* hout = mod ? g_h2[(t & 1) ^ 1] : g_h1[(t & 1) ^ 1];

            if (tid == 0) {
                mbar_arrive_tx(mb_h, 18432);
                bulk_g2s(s2u(hs), hin + rowBase * 72, 18432, mb_h);
                mbar_arrive_tx(mb_x, 65536);
                bulk_g2s(s2u(xbuf),
                         xgb + ((size_t)t * B_SZ + rowBase) * 256, 65536, mb_x);
            }
            mbar_wait(mb_h, (uint32_t)(t & 1));

            float acc[2][8][4];
#pragma unroll
            for (int i = 0; i < 2; i++)
#pragma unroll
                for (int j = 0; j < 8; j++)
#pragma unroll
                    for (int v = 0; v < 4; v++) acc[i][j][v] = 0.0f;

#pragma unroll
            for (int kk = 0; kk < 8; kk++) {
                uint32_t a[2][4];
#pragma unroll
                for (int mt = 0; mt < 2; mt++) {
                    int ar = (wm * 32 + mt * 16 + gp) * 72 + kk * 8 + tg * 2;
                    float2 lo = *(float2*)&hs[ar];
                    float2 hi = *(float2*)&hs[ar + 576];
                    a[mt][0] = __float_as_uint(lo.x);
                    a[mt][1] = __float_as_uint(hi.x);
                    a[mt][2] = __float_as_uint(lo.y);
                    a[mt][3] = __float_as_uint(hi.y);
                }
#pragma unroll
                for (int nt = 0; nt < 8; nt++) {
                    int br = (wn * 64 + nt * 8 + gp) * 72 + kk * 8 + tg * 2;
                    float2 bv = *(float2*)&ws[br];
                    uint32_t b[2] = {__float_as_uint(bv.x), __float_as_uint(bv.y)};
#pragma unroll
                    for (int mt = 0; mt < 2; mt++) mma_tf32(acc[mt][nt], a[mt], b);
                }
            }

#pragma unroll
            for (int mt = 0; mt < 2; mt++)
#pragma unroll
                for (int nt = 0; nt < 8; nt++) {
                    int r = wm * 32 + mt * 16 + gp;
                    int col = wn * 64 + nt * 8 + 2 * tg;
                    *(float2*)&gsm[r * 256 + col] = make_float2(acc[mt][nt][0], acc[mt][nt][1]);
                    *(float2*)&gsm[(r + 8) * 256 + col] = make_float2(acc[mt][nt][2], acc[mt][nt][3]);
                }
            __syncthreads();
            mbar_wait(mb_x, (uint32_t)(t & 1));

            for (int idx = tid; idx < 4096; idx += 256) {
                int kl = idx & 63, bl = idx >> 6;
                float4 gt = *(float4*)&gsm[bl * 256 + 4 * kl];
                int bg = rowBase + bl;
                float4 xv = *(float4*)&xbuf[bl * 256 + 4 * kl];
                float ii = sigm(gt.x + xv.x);
                float ff = sigm(gt.y + xv.y);
                float gg = tanhfast(gt.z + xv.z);
                float oo = sigm(gt.w + xv.w);
                float cold = cb[bg * 64 + kl];
                float cn = ff * cold + ii * gg;
                float hn = oo * tanhfast(cn);
                cb[bg * 64 + kl] = cn;
                hout[bg * 72 + swz(kl)] = tf32r(hn);
            }
            __syncthreads();
        }
    }
}

// ---------------- launch 5: head ----------------
__global__ void head_kernel(const float* __restrict__ w1, const float* __restrict__ b1,
                            const float* __restrict__ w2, const float* __restrict__ b2,
                            float* __restrict__ out) {
    __shared__ float hc[8 * 384];
    __shared__ float red[256];
    int tid = threadIdx.x;
    int rowBase = blockIdx.x * 8;

    for (int i = tid; i < 8 * 384; i += 256) {
        int r = i / 384, d = i - r * 384;
        int bg = rowBase + r;
        float v;
        if (d < 256)      v = g_h0[0][bg * 264 + swz(d)];
        else if (d < 320) v = g_h1[0][bg * 72 + swz(d - 256)];
        else              v = g_h2[0][bg * 72 + swz(d - 320)];
        hc[i] = v;
    }
    __syncthreads();

    for (int pass = 0; pass < 2; pass++) {
        int row = pass * 4 + (tid >> 6);
        int cell = tid & 63;
        const float* wr = w1 + cell * 384;
        const float* hr = hc + row * 384;
        float a = b1[cell];
#pragma unroll 4
        for (int d = 0; d < 384; d++) a += hr[d] * wr[d];
        a = fmaxf(a, 0.0f);
        red[tid] = a * w2[cell];
        __syncthreads();
        if (cell == 0) {
            float s = 0.0f;
#pragma unroll
            for (int j = 0; j < 64; j++) s += red[tid + j];
            out[rowBase + row] = s + b2[0];
        }
        __syncthreads();
    }
}

// ---------------- launch ----------------
extern "C" void kernel_launch(void* const* d_in, const int* in_sizes, int n_in,
                              void* d_out, int out_size) {
    const float* x0    = (const float*)d_in[0];
    const float* x1    = (const float*)d_in[1];
    const float* x2    = (const float*)d_in[2];
    const float* w_ih0 = (const float*)d_in[3];
    const float* w_hh0 = (const float*)d_in[4];
    const float* b_ih0 = (const float*)d_in[5];
    const float* b_hh0 = (const float*)d_in[6];
    const float* w_ih1 = (const float*)d_in[7];
    const float* w_hh1 = (const float*)d_in[8];
    const float* b_ih1 = (const float*)d_in[9];
    const float* b_hh1 = (const float*)d_in[10];
    const float* w_ih2 = (const float*)d_in[11];
    const float* w_hh2 = (const float*)d_in[12];
    const float* b_ih2 = (const float*)d_in[13];
    const float* b_hh2 = (const float*)d_in[14];
    const float* w1    = (const float*)d_in[15];
    const float* b1    = (const float*)d_in[16];
    const float* w2    = (const float*)d_in[17];
    const float* b2    = (const float*)d_in[18];
    float* out = (float*)d_out;

    cudaFuncSetAttribute(persist_kernel, cudaFuncAttributeMaxDynamicSharedMemorySize,
                         SMEM_PERSIST);
    cudaFuncSetAttribute(proj_all_kernel, cudaFuncAttributeMaxDynamicSharedMemorySize,
                         SMEM_PROJ);

    // launch 0
    prep_w_kernel<<<512, 256>>>(w_ih0, w_hh0, b_ih0, b_hh0,
                                w_ih1, w_hh1, b_ih1, b_hh1,
                                w_ih2, w_hh2, b_ih2, b_hh2);
    // launch 1
    prep_x_kernel<<<1024, 256>>>(x0, x1, x2);
    // launch 2
    init_kernel<<<256, 256>>>();
    // launch 3  (ncu capture index) — the projection GEMM
    proj_all_kernel<<<dim3(12, 512), 256, SMEM_PROJ>>>();
    // launch 4
    persist_kernel<<<NBLK, 256, SMEM_PERSIST>>>();
    // launch 5
    head_kernel<<<64, 256>>>(w1, b1, w2, b2, out);
}

// round 11
// speedup vs baseline: 1.3661x; 1.1695x over previous
#include <cuda_runtime.h>
#include <cstdint>

#define B_SZ 512
#define T_SZ 128
#define NBLK 144
#define SMEM_PERSIST 223360
#define SMEM_PROJ    61504

// ---------------- __device__ scratch (no allocations allowed) ----------------
// xg0: [t][bn(8)][b(512)][128]
__device__ __align__(128) float g_xg0[(size_t)T_SZ * 8 * B_SZ * 128];
__device__ __align__(128) float g_xg1[(size_t)T_SZ * B_SZ * 256];
__device__ __align__(128) float g_xg2[(size_t)T_SZ * B_SZ * 256];
// xp: [kt][row(65536)][20]  (16 quad-swizzled k-values + 4 pad)
__device__ __align__(128) float g_xp0[(size_t)19 * 65536 * 20];
__device__ __align__(128) float g_xp1[(size_t)5 * 65536 * 20];
__device__ __align__(128) float g_xp2[(size_t)3 * 65536 * 20];
// wih: [kt][gate][20]
__device__ __align__(128) float g_wih0[19 * 1024 * 20];
__device__ __align__(128) float g_wih1[5 * 256 * 20];
__device__ __align__(128) float g_wih2[3 * 256 * 20];
__device__ __align__(128) float g_whh0[1024 * 256];   // [gate][256], K pair-swizzled
__device__ __align__(128) float g_whh1[256 * 64];
__device__ __align__(128) float g_whh2[256 * 64];
__device__ __align__(128) float g_bias0[1024];
__device__ __align__(128) float g_bias1[256];
__device__ __align__(128) float g_bias2[256];
// h0: row-padded (264) so a 32-row tile is ONE contiguous bulk copy
__device__ __align__(128) float g_h0[2][B_SZ * 264];  // tf32, pair-swizzled
__device__ __align__(128) float g_h1[B_SZ * 72];      // final h only (written at t=127)
__device__ __align__(128) float g_h2[B_SZ * 72];
__device__ __align__(128) unsigned g_bar0[16 * 128];  // [bm][t] step barriers, target 8

// ---------------- helpers ----------------
__device__ __forceinline__ int swz(int k) {          // 8-group pair swizzle (h / whh)
    return (k & ~7) | ((k & 3) << 1) | ((k >> 2) & 1);
}
__device__ __forceinline__ int swz16q(int k) {       // 16-group quad swizzle (xp / wih)
    // pos = tg*4 + kk*2 + half :  one LDS.128 at tg*4 -> fragments for BOTH k8 steps
    return ((k & 3) << 2) | ((k >> 3) << 1) | ((k >> 2) & 1);
}

__device__ __forceinline__ float tf32r(float x) {
    uint32_t u;
    asm("cvt.rna.tf32.f32 %0, %1;" : "=r"(u) : "f"(x));
    return __uint_as_float(u);
}

__device__ __forceinline__ void mma_tf32(float c[4], const uint32_t a[4], const uint32_t b[2]) {
    asm volatile(
        "mma.sync.aligned.m16n8k8.row.col.f32.tf32.tf32.f32 "
        "{%0,%1,%2,%3}, {%4,%5,%6,%7}, {%8,%9}, {%0,%1,%2,%3};"
        : "+f"(c[0]), "+f"(c[1]), "+f"(c[2]), "+f"(c[3])
        : "r"(a[0]), "r"(a[1]), "r"(a[2]), "r"(a[3]), "r"(b[0]), "r"(b[1]));
}

__device__ __forceinline__ float fex2(float x) {
    float r; asm("ex2.approx.f32 %0, %1;" : "=f"(r) : "f"(x)); return r;
}
__device__ __forceinline__ float frcp(float x) {
    float r; asm("rcp.approx.f32 %0, %1;" : "=f"(r) : "f"(x)); return r;
}
__device__ __forceinline__ float sigm(float x) {
    return frcp(1.0f + fex2(-1.4426950408889634f * x));
}
__device__ __forceinline__ float tanhfast(float x) {
    return 2.0f * frcp(1.0f + fex2(-2.8853900817779268f * x)) - 1.0f;
}

// ---- bulk-copy + mbarrier primitives ----
__device__ __forceinline__ uint32_t s2u(const void* p) {
    return (uint32_t)__cvta_generic_to_shared(p);
}
__device__ __forceinline__ void mbar_init(uint32_t mb, uint32_t cnt) {
    asm volatile("mbarrier.init.shared.b64 [%0], %1;" :: "r"(mb), "r"(cnt) : "memory");
}
__device__ __forceinline__ void mbar_arrive_tx(uint32_t mb, uint32_t bytes) {
    asm volatile("mbarrier.arrive.expect_tx.shared.b64 _, [%0], %1;"
                 :: "r"(mb), "r"(bytes) : "memory");
}
__device__ __forceinline__ void mbar_wait(uint32_t mb, uint32_t parity) {
    asm volatile(
        "{\n\t.reg .pred P;\n"
        "W%=:\n\t"
        "mbarrier.try_wait.parity.shared.b64 P, [%0], %1;\n\t"
        "@!P bra W%=;\n\t}"
        :: "r"(mb), "r"(parity) : "memory");
}
__device__ __forceinline__ void bulk_g2s(uint32_t dst, const void* src,
                                         uint32_t bytes, uint32_t mb) {
    asm volatile(
        "cp.async.bulk.shared::cluster.global.mbarrier::complete_tx::bytes "
        "[%0], [%1], %2, [%3];"
        :: "r"(dst), "l"(src), "r"(bytes), "r"(mb) : "memory");
}
#define FENCE_ASYNC asm volatile("fence.proxy.async.shared::cta;" ::: "memory")

// ---------------- launch 0: prep weights ----------------
__global__ void prep_w_kernel(
    const float* __restrict__ wih0, const float* __restrict__ whh0,
    const float* __restrict__ bih0, const float* __restrict__ bhh0,
    const float* __restrict__ wih1, const float* __restrict__ whh1,
    const float* __restrict__ bih1, const float* __restrict__ bhh1,
    const float* __restrict__ wih2, const float* __restrict__ whh2,
    const float* __restrict__ bih2, const float* __restrict__ bhh2)
{
    size_t stride = (size_t)gridDim.x * blockDim.x;
    size_t t0 = (size_t)blockIdx.x * blockDim.x + threadIdx.x;

    // wih -> [kt][gate'][20], gate-interleaved rows g' = 4k+q, quad swizzle within 16
    for (size_t ii = t0; ii < 1024 * 304; ii += stride) {
        int i = (int)ii;
        int gp = i / 304, dp = i - gp * 304;
        int k = gp >> 2, q = gp & 3, go = q * 256 + k;
        g_wih0[((size_t)(dp >> 4) * 1024 + gp) * 20 + swz16q(dp & 15)] =
            (dp < 300) ? tf32r(wih0[go * 300 + dp]) : 0.0f;
    }
    for (size_t ii = t0; ii < 256 * 80; ii += stride) {
        int i = (int)ii;
        int gp = i / 80, dp = i - gp * 80;
        int k = gp >> 2, q = gp & 3, go = q * 64 + k;
        g_wih1[((size_t)(dp >> 4) * 256 + gp) * 20 + swz16q(dp & 15)] =
            (dp < 74) ? tf32r(wih1[go * 74 + dp]) : 0.0f;
    }
    for (size_t ii = t0; ii < 256 * 48; ii += stride) {
        int i = (int)ii;
        int gp = i / 48, dp = i - gp * 48;
        int k = gp >> 2, q = gp & 3, go = q * 64 + k;
        g_wih2[((size_t)(dp >> 4) * 256 + gp) * 20 + swz16q(dp & 15)] =
            (dp < 35) ? tf32r(wih2[go * 35 + dp]) : 0.0f;
    }
    // whh keeps the 8-group pair swizzle (persist layout unchanged)
    for (size_t ii = t0; ii < 1024 * 256; ii += stride) {
        int i = (int)ii;
        int gp = i >> 8, dp = i & 255;
        int k = gp >> 2, q = gp & 3, go = q * 256 + k;
        g_whh0[gp * 256 + swz(dp)] = tf32r(whh0[go * 256 + dp]);
    }
    for (size_t ii = t0; ii < 256 * 64; ii += stride) {
        int i = (int)ii;
        int gp = i >> 6, dp = i & 63;
        int k = gp >> 2, q = gp & 3, go = q * 64 + k;
        g_whh1[gp * 64 + swz(dp)] = tf32r(whh1[go * 64 + dp]);
        g_whh2[gp * 64 + swz(dp)] = tf32r(whh2[go * 64 + dp]);
    }
    for (size_t ii = t0; ii < 1024; ii += stride) {
        int i = (int)ii;
        int k = i >> 2, q = i & 3, go = q * 256 + k;
        g_bias0[i] = bih0[go] + bhh0[go];
    }
    for (size_t ii = t0; ii < 256; ii += stride) {
        int i = (int)ii;
        int k = i >> 2, q = i & 3, go = q * 64 + k;
        g_bias1[i] = bih1[go] + bhh1[go];
        g_bias2[i] = bih2[go] + bhh2[go];
    }
}

// ---------------- launch 1: pad x -> xp + init state/barriers ----------------
__device__ __forceinline__ void prep_x_one(
    const float* __restrict__ X, float* __restrict__ XP,
    int D, int KT, size_t task0, size_t stride)
{
    size_t ntask = (size_t)KT * 65536;
    for (size_t i = task0; i < ntask; i += stride) {
        int kt = (int)(i >> 16);
        int r = (int)(i & 65535);
        int k0 = kt * 16;
        float o[20];
#pragma unroll
        for (int c = 0; c < 16; c++) {
            int d = k0 + c;
            o[swz16q(c)] = (d < D) ? tf32r(X[(size_t)r * D + d]) : 0.0f;
        }
        o[16] = o[17] = o[18] = o[19] = 0.0f;
        float4* dst = (float4*)&XP[i * 20];
#pragma unroll
        for (int v = 0; v < 5; v++) dst[v] = *(float4*)&o[v * 4];
    }
}

__global__ void prep_x_kernel(
    const float* __restrict__ x0, const float* __restrict__ x1, const float* __restrict__ x2)
{
    size_t stride = (size_t)gridDim.x * blockDim.x;
    size_t t0 = (size_t)blockIdx.x * blockDim.x + threadIdx.x;
    prep_x_one(x0, g_xp0, 300, 19, t0, stride);
    prep_x_one(x1, g_xp1, 74, 5, t0, stride);
    prep_x_one(x2, g_xp2, 35, 3, t0, stride);
    // init: h0 ping buffer + step barriers
    for (size_t i = t0; i < B_SZ * 264; i += stride) g_h0[0][i] = 0.0f;
    for (size_t i = t0; i < 16 * 128; i += stride) g_bar0[i] = 0u;
}

// ---------------- launch 2: projections, 128x128 tiles, LDS.128 fragments ----------
__device__ __forceinline__ void proj_impl(
    const float* __restrict__ XP, const float* __restrict__ W,
    const float* __restrict__ bias, float* __restrict__ XG,
    int G, int KT, int colBase, int rowBase, float* psm)
{
    int tid = threadIdx.x, lane = tid & 31, warp = tid >> 5;
    int gp = lane >> 2, tg = lane & 3;
    int wm = warp >> 1, wn = warp & 1; // 4m x 2n warps; warp tile 32 x 64

    uint32_t mb = s2u(psm);       // 3 mbarriers
    float* buf = psm + 32;

    if (tid == 0) {
        mbar_init(mb, 1); mbar_init(mb + 8, 1); mbar_init(mb + 16, 1);
        FENCE_ASYNC;
    }
    __syncthreads();

    float acc[2][8][4];
#pragma unroll
    for (int i = 0; i < 2; i++)
#pragma unroll
        for (int j = 0; j < 8; j++)
#pragma unroll
            for (int v = 0; v < 4; v++) acc[i][j][v] = 0.0f;

    auto issue = [&](int kt, int s) {
        if (tid == 0) {
            float* xd = buf + s * 5120;
            float* wd = xd + 2560;
            uint32_t m = mb + 8u * s;
            mbar_arrive_tx(m, 20480);
            bulk_g2s(s2u(xd), XP + ((size_t)kt * 65536 + rowBase) * 20, 10240, m);
            bulk_g2s(s2u(wd), W + ((size_t)kt * G + colBase) * 20, 10240, m);
        }
    };

    issue(0, 0);
    issue(1, 1);

    for (int kt = 0; kt < KT; kt++) {
        int s = kt % 3;
        mbar_wait(mb + 8u * s, (uint32_t)((kt / 3) & 1));
        float* xb = buf + s * 5120;
        float* wb = xb + 2560;

        uint32_t a[2][2][4]; // [kk][mt]
#pragma unroll
        for (int mt = 0; mt < 2; mt++) {
            int ar = (wm * 32 + mt * 16 + gp) * 20 + tg * 4;
            float4 lo = *(float4*)&xb[ar];
            float4 hi = *(float4*)&xb[ar + 160];
            a[0][mt][0] = __float_as_uint(lo.x); a[0][mt][1] = __float_as_uint(hi.x);
            a[0][mt][2] = __float_as_uint(lo.y); a[0][mt][3] = __float_as_uint(hi.y);
            a[1][mt][0] = __float_as_uint(lo.z); a[1][mt][1] = __float_as_uint(hi.z);
            a[1][mt][2] = __float_as_uint(lo.w); a[1][mt][3] = __float_as_uint(hi.w);
        }
#pragma unroll
        for (int nt = 0; nt < 8; nt++) {
            int br = (wn * 64 + nt * 8 + gp) * 20 + tg * 4;
            float4 bv = *(float4*)&wb[br];
            uint32_t b0[2] = {__float_as_uint(bv.x), __float_as_uint(bv.y)};
            uint32_t b1[2] = {__float_as_uint(bv.z), __float_as_uint(bv.w)};
#pragma unroll
            for (int mt = 0; mt < 2; mt++) mma_tf32(acc[mt][nt], a[0][mt], b0);
#pragma unroll
            for (int mt = 0; mt < 2; mt++) mma_tf32(acc[mt][nt], a[1][mt], b1);
        }
        __syncthreads();
        if (kt + 2 < KT) issue(kt + 2, (kt + 2) % 3);
    }

#pragma unroll
    for (int mt = 0; mt < 2; mt++)
#pragma unroll
        for (int nt = 0; nt < 8; nt++) {
            int r0 = rowBase + wm * 32 + mt * 16 + gp;
            int col = colBase + wn * 64 + nt * 8 + 2 * tg;
            float bx = bias[col], by = bias[col + 1];
            int tt0 = r0 & 127, bb0 = r0 >> 7;
            int r1 = r0 + 8;
            int tt1 = r1 & 127, bb1 = r1 >> 7;
            size_t o0, o1;
            if (G == 1024) {
                int bnn = col >> 7, cl = col & 127;
                o0 = (((size_t)tt0 * 8 + bnn) * B_SZ + bb0) * 128 + cl;
                o1 = (((size_t)tt1 * 8 + bnn) * B_SZ + bb1) * 128 + cl;
            } else {
                o0 = ((size_t)tt0 * B_SZ + bb0) * 256 + col;
                o1 = ((size_t)tt1 * B_SZ + bb1) * 256 + col;
            }
            *(float2*)&XG[o0] = make_float2(acc[mt][nt][0] + bx, acc[mt][nt][1] + by);
            *(float2*)&XG[o1] = make_float2(acc[mt][nt][2] + bx, acc[mt][nt][3] + by);
        }
}

__global__ __launch_bounds__(256, 2) void proj_all_kernel() {
    extern __shared__ __align__(16) float psm[];
    int bx = blockIdx.x;
    int rowBase = blockIdx.y * 128;
    if (bx < 8) {
        proj_impl(g_xp0, g_wih0, g_bias0, g_xg0, 1024, 19, bx * 128, rowBase, psm);
    } else if (bx < 10) {
        proj_impl(g_xp1, g_wih1, g_bias1, g_xg1, 256, 5, (bx - 8) * 128, rowBase, psm);
    } else {
        proj_impl(g_xp2, g_wih2, g_bias2, g_xg2, 256, 3, (bx - 10) * 128, rowBase, psm);
    }
}

// ---------------- launch 3 (ncu capture index): persistent recurrence ----------------
// blocks 0..127  : m0, 32 rows x 128 gate cols; per-(bm,t) 8-block barrier (replay-safe)
// blocks 128..143: m1/m2, 64 rows x all 256 gate cols; h in SMEM, c in regs, no gmem h
__global__ __launch_bounds__(256, 1) void persist_kernel() {
    extern __shared__ __align__(16) float sm[];
    int bid = blockIdx.x, tid = threadIdx.x;
    int lane = tid & 31, warp = tid >> 5;
    int gp = lane >> 2, tg = lane & 3;

    if (bid < 128) {
        // ================= module 0: H=256, G=1024 =================
        int bm = bid >> 3, bn = bid & 7;
        int rowBase = bm * 32, colBase = bn * 128;
        float* hs   = sm + 32;         // 32 x 264
        float* xbuf = hs + 8448;       // 32 x 128
        float* gsm  = xbuf + 4096;     // 32 x 128
        uint32_t mb_h = s2u(sm);
        uint32_t mb_x = mb_h + 8;

        if (tid == 0) { mbar_init(mb_h, 1); mbar_init(mb_x, 1); FENCE_ASYNC; }
        __syncthreads();

        // weights resident in registers: warp wn owns cols [wn*16, wn*16+16), all K
        int wn = warp;
        uint32_t breg[32][2][2];
#pragma unroll
        for (int kk = 0; kk < 32; kk++)
#pragma unroll
            for (int nt = 0; nt < 2; nt++) {
                float2 v = *(const float2*)
                    &g_whh0[(size_t)(colBase + wn * 16 + nt * 8 + gp) * 256 + kk * 8 + tg * 2];
                breg[kk][nt][0] = __float_as_uint(v.x);
                breg[kk][nt][1] = __float_as_uint(v.y);
            }

        float creg[4] = {0.0f, 0.0f, 0.0f, 0.0f};

        // prefetch xg for t=0
        if (tid == 0) {
            mbar_arrive_tx(mb_x, 16384);
            bulk_g2s(s2u(xbuf), g_xg0 + ((size_t)bn * B_SZ + rowBase) * 128, 16384, mb_x);
        }

        for (int t = 0; t < T_SZ; t++) {
            const float* hin = g_h0[t & 1];
            float* hout = g_h0[(t & 1) ^ 1];

            if (tid == 0) {
                mbar_arrive_tx(mb_h, 33792);
                bulk_g2s(s2u(hs), hin + rowBase * 264, 33792, mb_h);
            }
            mbar_wait(mb_h, (uint32_t)(t & 1));

            float acc[2][2][4];
#pragma unroll
            for (int i = 0; i < 2; i++)
#pragma unroll
                for (int j = 0; j < 2; j++)
#pragma unroll
                    for (int v = 0; v < 4; v++) acc[i][j][v] = 0.0f;

#pragma unroll
            for (int kk = 0; kk < 32; kk++) {
                int kb = kk * 8 + tg * 2;
                float2 lo0 = *(float2*)&hs[gp * 264 + kb];
                float2 hi0 = *(float2*)&hs[(gp + 8) * 264 + kb];
                float2 lo1 = *(float2*)&hs[(gp + 16) * 264 + kb];
                float2 hi1 = *(float2*)&hs[(gp + 24) * 264 + kb];
                uint32_t a0[4] = {__float_as_uint(lo0.x), __float_as_uint(hi0.x),
                                  __float_as_uint(lo0.y), __float_as_uint(hi0.y)};
                uint32_t a1[4] = {__float_as_uint(lo1.x), __float_as_uint(hi1.x),
                                  __float_as_uint(lo1.y), __float_as_uint(hi1.y)};
                mma_tf32(acc[0][0], a0, breg[kk][0]);
                mma_tf32(acc[0][1], a0, breg[kk][1]);
                mma_tf32(acc[1][0], a1, breg[kk][0]);
                mma_tf32(acc[1][1], a1, breg[kk][1]);
            }

#pragma unroll
            for (int mt = 0; mt < 2; mt++)
#pragma unroll
                for (int nt = 0; nt < 2; nt++) {
                    int r = mt * 16 + gp, col = wn * 16 + nt * 8 + tg * 2;
                    *(float2*)&gsm[r * 128 + col] =
                        make_float2(acc[mt][nt][0], acc[mt][nt][1]);
                    *(float2*)&gsm[(r + 8) * 128 + col] =
                        make_float2(acc[mt][nt][2], acc[mt][nt][3]);
                }
            __syncthreads();
            mbar_wait(mb_x, (uint32_t)(t & 1));

#pragma unroll
            for (int j = 0; j < 4; j++) {
                int idx = tid + j * 256;
                int bl = idx >> 5, kl = idx & 31;
                float4 gt = *(float4*)&gsm[bl * 128 + 4 * kl];
                float4 xv = *(float4*)&xbuf[bl * 128 + 4 * kl];
                float ii = sigm(gt.x + xv.x);
                float ff = sigm(gt.y + xv.y);
                float gg = tanhfast(gt.z + xv.z);
                float oo = sigm(gt.w + xv.w);
                float cn = ff * creg[j] + ii * gg;
                creg[j] = cn;
                float hn = oo * tanhfast(cn);
                hout[(rowBase + bl) * 264 + swz(bn * 32 + kl)] = tf32r(hn);
            }

            if (t + 1 < T_SZ) {
                __syncthreads();   // all cell updates + xbuf reads complete
                if (tid == 0) {
                    // prefetch next xg while we wait at the barrier
                    mbar_arrive_tx(mb_x, 16384);
                    bulk_g2s(s2u(xbuf),
                             g_xg0 + (((size_t)(t + 1) * 8 + bn) * B_SZ + rowBase) * 128,
                             16384, mb_x);
                    __threadfence();
                    unsigned* c = &g_bar0[bm * 128 + t];
                    atomicAdd(c, 1u);
                    while (*(volatile unsigned*)c < 8u) {}
                    __threadfence();
                    // replay-safe delayed reset: everyone passed barrier[t-1] long ago
                    if (bn == 0 && t > 0) g_bar0[bm * 128 + t - 1] = 0u;
                }
                __syncthreads();
            }
        }
        // reset last-used barrier for replay safety (all peers are in step 127 by now)
        if (tid == 0 && bn == 0) g_bar0[bm * 128 + 126] = 0u;
    } else {
        // ================= modules 1,2: H=64, G=256, fully self-contained ==========
        int sub = bid - 128;
        int mod = sub >> 3, bm = sub & 7;
        int rowBase = bm * 64;
        const float* whh = mod ? g_whh2 : g_whh1;
        const float* xgb = mod ? g_xg2 : g_xg1;
        float* hfin = mod ? g_h2 : g_h1;

        float* ws   = sm + 32;         // 256 x 72
        float* hs   = ws + 18432;      // 64 x 72   (persistent across steps!)
        float* gsm  = hs + 4608;       // 64 x 256
        float* xbuf = gsm + 16384;     // 64 x 256
        uint32_t mb_x = s2u(sm);

        if (tid == 0) { mbar_init(mb_x, 1); FENCE_ASYNC; }

        for (int idx = tid; idx < 256 * 16; idx += 256) {
            int r = idx >> 4, c = idx & 15;
            *(float4*)&ws[r * 72 + c * 4] = *(const float4*)&whh[r * 64 + c * 4];
        }
        for (int idx = tid; idx < 64 * 72; idx += 256) hs[idx] = 0.0f;  // h(0) = 0
        __syncthreads();

        // c state in registers: fixed (bl, kl) per (tid, j) across all steps
        float creg[16];
#pragma unroll
        for (int j = 0; j < 16; j++) creg[j] = 0.0f;

        // prefetch xg for t=0
        if (tid == 0) {
            mbar_arrive_tx(mb_x, 65536);
            bulk_g2s(s2u(xbuf), xgb + (size_t)rowBase * 256, 65536, mb_x);
        }

        int wm = warp >> 2, wn = warp & 3;

        for (int t = 0; t < T_SZ; t++) {
            float acc[2][8][4];
#pragma unroll
            for (int i = 0; i < 2; i++)
#pragma unroll
                for (int j = 0; j < 8; j++)
#pragma unroll
                    for (int v = 0; v < 4; v++) acc[i][j][v] = 0.0f;

#pragma unroll
            for (int kk = 0; kk < 8; kk++) {
                uint32_t a[2][4];
#pragma unroll
                for (int mt = 0; mt < 2; mt++) {
                    int ar = (wm * 32 + mt * 16 + gp) * 72 + kk * 8 + tg * 2;
                    float2 lo = *(float2*)&hs[ar];
                    float2 hi = *(float2*)&hs[ar + 576];
                    a[mt][0] = __float_as_uint(lo.x);
                    a[mt][1] = __float_as_uint(hi.x);
                    a[mt][2] = __float_as_uint(lo.y);
                    a[mt][3] = __float_as_uint(hi.y);
                }
#pragma unroll
                for (int nt = 0; nt < 8; nt++) {
                    int br = (wn * 64 + nt * 8 + gp) * 72 + kk * 8 + tg * 2;
                    float2 bv = *(float2*)&ws[br];
                    uint32_t b[2] = {__float_as_uint(bv.x), __float_as_uint(bv.y)};
#pragma unroll
                    for (int mt = 0; mt < 2; mt++) mma_tf32(acc[mt][nt], a[mt], b);
                }
            }

#pragma unroll
            for (int mt = 0; mt < 2; mt++)
#pragma unroll
                for (int nt = 0; nt < 8; nt++) {
                    int r = wm * 32 + mt * 16 + gp;
                    int col = wn * 64 + nt * 8 + 2 * tg;
                    *(float2*)&gsm[r * 256 + col] = make_float2(acc[mt][nt][0], acc[mt][nt][1]);
                    *(float2*)&gsm[(r + 8) * 256 + col] = make_float2(acc[mt][nt][2], acc[mt][nt][3]);
                }
            __syncthreads();           // gsm ready; also: everyone done reading hs
            mbar_wait(mb_x, (uint32_t)(t & 1));

#pragma unroll
            for (int j = 0; j < 16; j++) {
                int idx = tid + j * 256;
                int kl = idx & 63, bl = idx >> 6;
                float4 gt = *(float4*)&gsm[bl * 256 + 4 * kl];
                float4 xv = *(float4*)&xbuf[bl * 256 + 4 * kl];
                float ii = sigm(gt.x + xv.x);
                float ff = sigm(gt.y + xv.y);
                float gg = tanhfast(gt.z + xv.z);
                float oo = sigm(gt.w + xv.w);
                float cn = ff * creg[j] + ii * gg;
                creg[j] = cn;
                float hn = tf32r(oo * tanhfast(cn));
                if (t + 1 < T_SZ) {
                    hs[bl * 72 + swz(kl)] = hn;          // stays local
                } else {
                    hfin[(rowBase + bl) * 72 + swz(kl)] = hn;  // final -> gmem for head
                }
            }
            __syncthreads();           // hs updated + xbuf reads complete
            if (tid == 0 && t + 1 < T_SZ) {
                mbar_arrive_tx(mb_x, 65536);
                bulk_g2s(s2u(xbuf),
                         xgb + ((size_t)(t + 1) * B_SZ + rowBase) * 256, 65536, mb_x);
            }
        }
    }
}

// ---------------- launch 4: head ----------------
__global__ void head_kernel(const float* __restrict__ w1, const float* __restrict__ b1,
                            const float* __restrict__ w2, const float* __restrict__ b2,
                            float* __restrict__ out) {
    __shared__ float hc[8 * 384];
    __shared__ float red[256];
    int tid = threadIdx.x;
    int rowBase = blockIdx.x * 8;

    for (int i = tid; i < 8 * 384; i += 256) {
        int r = i / 384, d = i - r * 384;
        int bg = rowBase + r;
        float v;
        if (d < 256)      v = g_h0[0][bg * 264 + swz(d)];
        else if (d < 320) v = g_h1[bg * 72 + swz(d - 256)];
        else              v = g_h2[bg * 72 + swz(d - 320)];
        hc[i] = v;
    }
    __syncthreads();

    for (int pass = 0; pass < 2; pass++) {
        int row = pass * 4 + (tid >> 6);
        int cell = tid & 63;
        const float* wr = w1 + cell * 384;
        const float* hr = hc + row * 384;
        float a = b1[cell];
#pragma unroll 4
        for (int d = 0; d < 384; d++) a += hr[d] * wr[d];
        a = fmaxf(a, 0.0f);
        red[tid] = a * w2[cell];
        __syncthreads();
        if (cell == 0) {
            float s = 0.0f;
#pragma unroll
            for (int j = 0; j < 64; j++) s += red[tid + j];
            out[rowBase + row] = s + b2[0];
        }
        __syncthreads();
    }
}

// ---------------- launch ----------------
extern "C" void kernel_launch(void* const* d_in, const int* in_sizes, int n_in,
                              void* d_out, int out_size) {
    const float* x0    = (const float*)d_in[0];
    const float* x1    = (const float*)d_in[1];
    const float* x2    = (const float*)d_in[2];
    const float* w_ih0 = (const float*)d_in[3];
    const float* w_hh0 = (const float*)d_in[4];
    const float* b_ih0 = (const float*)d_in[5];
    const float* b_hh0 = (const float*)d_in[6];
    const float* w_ih1 = (const float*)d_in[7];
    const float* w_hh1 = (const float*)d_in[8];
    const float* b_ih1 = (const float*)d_in[9];
    const float* b_hh1 = (const float*)d_in[10];
    const float* w_ih2 = (const float*)d_in[11];
    const float* w_hh2 = (const float*)d_in[12];
    const float* b_ih2 = (const float*)d_in[13];
    const float* b_hh2 = (const float*)d_in[14];
    const float* w1    = (const float*)d_in[15];
    const float* b1    = (const float*)d_in[16];
    const float* w2    = (const float*)d_in[17];
    const float* b2    = (const float*)d_in[18];
    float* out = (float*)d_out;

    cudaFuncSetAttribute(persist_kernel, cudaFuncAttributeMaxDynamicSharedMemorySize,
                         SMEM_PERSIST);
    cudaFuncSetAttribute(proj_all_kernel, cudaFuncAttributeMaxDynamicSharedMemorySize,
                         SMEM_PROJ);

    // launch 0
    prep_w_kernel<<<512, 256>>>(w_ih0, w_hh0, b_ih0, b_hh0,
                                w_ih1, w_hh1, b_ih1, b_hh1,
                                w_ih2, w_hh2, b_ih2, b_hh2);
    // launch 1 (includes state init)
    prep_x_kernel<<<1024, 256>>>(x0, x1, x2);
    // launch 2
    proj_all_kernel<<<dim3(12, 512), 256, SMEM_PROJ>>>();
    // launch 3 (ncu capture index) — the persistent recurrence, now replay-safe
    persist_kernel<<<NBLK, 256, SMEM_PERSIST>>>();
    // launch 4
    head_kernel<<<64, 256>>>(w1, b1, w2, b2, out);
}